// round 2
// baseline (speedup 1.0000x reference)
#include <cuda_runtime.h>
#include <math.h>

// Problem dims
#define Bc  2
#define Sc  2048
#define Dc  2048
#define Hc  16
#define HDc 128

static const int TOT = Bc * Sc * Dc;  // 8388608

// Scratch (allocation-free rule: __device__ globals)
__device__ float g_q[Bc * Sc * Dc];
__device__ float g_k[Bc * Sc * Dc];
__device__ float g_v[Bc * Sc * Dc];
__device__ float g_o[Bc * Sc * Dc];

__device__ __forceinline__ void fma4(float4& o, float s, const float4& b) {
    o.x += s * b.x; o.y += s * b.y; o.z += s * b.z; o.w += s * b.w;
}

// ---------------------------------------------------------------------------
// GEMM: C[4096 x 2048] = A[4096 x 2048] @ W[2048 x 2048], fp32
// Tiles 128x64x16, 256 threads, 8x4 micro-tile (rows split 4+4 for bank spread)
// ---------------------------------------------------------------------------
__global__ __launch_bounds__(256) void gemm128x64(
    const float* __restrict__ A, const float* __restrict__ W, float* __restrict__ C)
{
    __shared__ float As[16][132];   // A transposed: As[k][m]
    __shared__ float Bs[16][68];    // Bs[k][n]

    const int t  = threadIdx.x;
    const int m0 = blockIdx.y * 128;
    const int n0 = blockIdx.x * 64;
    const int tr = t >> 4;          // 0..15
    const int tc = t & 15;          // 0..15

    float4 acc[8];
#pragma unroll
    for (int i = 0; i < 8; ++i) acc[i] = make_float4(0.f, 0.f, 0.f, 0.f);

    const int brow = t >> 4;
    const int bcc  = t & 15;

    for (int kt = 0; kt < 2048; kt += 16) {
        // Load A tile (128x16), transpose into As
#pragma unroll
        for (int u = 0; u < 2; ++u) {
            int fa  = u * 256 + t;
            int row = fa >> 2;
            int kc  = fa & 3;
            float4 av = *(const float4*)&A[(size_t)(m0 + row) * 2048 + kt + kc * 4];
            As[kc * 4 + 0][row] = av.x;
            As[kc * 4 + 1][row] = av.y;
            As[kc * 4 + 2][row] = av.z;
            As[kc * 4 + 3][row] = av.w;
        }
        // Load B tile (16x64)
        {
            float4 bv = *(const float4*)&W[(size_t)(kt + brow) * 2048 + n0 + bcc * 4];
            *(float4*)&Bs[brow][bcc * 4] = bv;
        }
        __syncthreads();

#pragma unroll
        for (int k = 0; k < 16; ++k) {
            float4 a0 = *(float4*)&As[k][4 * tr];
            float4 a1 = *(float4*)&As[k][64 + 4 * tr];
            float4 b  = *(float4*)&Bs[k][4 * tc];
            fma4(acc[0], a0.x, b); fma4(acc[1], a0.y, b);
            fma4(acc[2], a0.z, b); fma4(acc[3], a0.w, b);
            fma4(acc[4], a1.x, b); fma4(acc[5], a1.y, b);
            fma4(acc[6], a1.z, b); fma4(acc[7], a1.w, b);
        }
        __syncthreads();
    }

#pragma unroll
    for (int ri = 0; ri < 4; ++ri)
        *(float4*)&C[(size_t)(m0 + 4 * tr + ri) * 2048 + n0 + 4 * tc] = acc[ri];
#pragma unroll
    for (int ri = 0; ri < 4; ++ri)
        *(float4*)&C[(size_t)(m0 + 64 + 4 * tr + ri) * 2048 + n0 + 4 * tc] = acc[4 + ri];
}

// ---------------------------------------------------------------------------
// Rotary (in-place on q and k), one thread per (b,s,h,j<64) pair
// ---------------------------------------------------------------------------
__global__ void rotary_kernel(float* __restrict__ q, float* __restrict__ k)
{
    int idx = blockIdx.x * blockDim.x + threadIdx.x;
    if (idx >= Bc * Sc * Hc * 64) return;
    int j = idx & 63;
    int h = (idx >> 6) & (Hc - 1);
    int s = (idx >> 10) & (Sc - 1);
    int b = idx >> 21;

    float fraction = (float)j * (1.0f / 64.0f);     // 2*j/128
    float inv_freq = 1.0f / powf(10000.0f, fraction);
    float ang = (float)s * inv_freq;
    float sn, cs;
    sincosf(ang, &sn, &cs);

    size_t base = ((size_t)(b * Sc + s)) * Dc + h * HDc + j;
    float q1 = q[base], q2 = q[base + 64];
    q[base]      = q1 * cs - q2 * sn;
    q[base + 64] = q2 * cs + q1 * sn;
    float k1 = k[base], k2 = k[base + 64];
    k[base]      = k1 * cs - k2 * sn;
    k[base + 64] = k2 * cs + k1 * sn;
}

// ---------------------------------------------------------------------------
// Flash attention, causal, tanh cap, Lingvo softmax (phantom 0-logit:
// init m=0, l=1). fp32. 64 q-rows per CTA, 64-wide KV tiles, 256 threads.
// Q/K/V/O layout: [B, S, D] with head h at columns h*128..h*128+127.
// ---------------------------------------------------------------------------
#define FLASH_SMEM_FLOATS (64*128 + 128*65 + 64*128 + 64*65)

__global__ __launch_bounds__(256) void flash_attn(
    const float* __restrict__ Q, const float* __restrict__ K,
    const float* __restrict__ V, float* __restrict__ O)
{
    extern __shared__ float sm[];
    float* sQ  = sm;                    // [64][128]
    float* sKT = sm + 64 * 128;         // [128][65]  (K transposed)
    float* sV  = sKT + 128 * 65;        // [64][128]
    float* sS  = sV + 64 * 128;         // [64][65]

    const int t  = threadIdx.x;
    const int qi = blockIdx.x;          // q tile 0..31
    const int h  = blockIdx.y;
    const int b  = blockIdx.z;
    const size_t base = (size_t)b * Sc * Dc + (size_t)h * HDc;

    // Load Q tile
#pragma unroll
    for (int it = 0; it < 8; ++it) {
        int f = it * 256 + t;
        int row = f >> 5, dc = f & 31;
        float4 v4 = *(const float4*)&Q[base + (size_t)(qi * 64 + row) * Dc + dc * 4];
        *(float4*)&sQ[row * 128 + dc * 4] = v4;
    }

    float m = 0.f, l = 1.f;             // phantom logit 0 => Lingvo denom
    float4 o[8];
#pragma unroll
    for (int u = 0; u < 8; ++u) o[u] = make_float4(0.f, 0.f, 0.f, 0.f);

    const int r  = t >> 2;              // row 0..63 (softmax/PV mapping)
    const int qq = t & 3;               // quarter
    const int tr = t >> 4, tc = t & 15; // QK 4x4 micro mapping

    for (int j = 0; j <= qi; ++j) {
        __syncthreads();
        // Load K (transposed, stride 65: conflict-free stores) and V
#pragma unroll
        for (int it = 0; it < 8; ++it) {
            int f = it * 256 + t;
            int wIdx = f >> 5;
            int half = wIdx & 1;
            int rb   = (wIdx >> 1) << 1;
            int ln   = f & 31;
            int srow = rb + (ln >> 4);
            int dc   = half * 16 + (ln & 15);
            float4 kv = *(const float4*)&K[base + (size_t)(j * 64 + srow) * Dc + dc * 4];
            sKT[(dc * 4 + 0) * 65 + srow] = kv.x;
            sKT[(dc * 4 + 1) * 65 + srow] = kv.y;
            sKT[(dc * 4 + 2) * 65 + srow] = kv.z;
            sKT[(dc * 4 + 3) * 65 + srow] = kv.w;

            int rowv = f >> 5, dcv = f & 31;
            float4 vv = *(const float4*)&V[base + (size_t)(j * 64 + rowv) * Dc + dcv * 4];
            *(float4*)&sV[rowv * 128 + dcv * 4] = vv;
        }
        __syncthreads();

        // S = Q K^T, 4x4 per thread
        float acc[4][4];
#pragma unroll
        for (int a = 0; a < 4; ++a)
#pragma unroll
            for (int c = 0; c < 4; ++c) acc[a][c] = 0.f;

#pragma unroll 4
        for (int k0 = 0; k0 < 128; k0 += 4) {
            float4 qv[4];
#pragma unroll
            for (int a = 0; a < 4; ++a)
                qv[a] = *(float4*)&sQ[(4 * tr + a) * 128 + k0];
            float kt[4][4];
#pragma unroll
            for (int kk = 0; kk < 4; ++kk)
#pragma unroll
                for (int c = 0; c < 4; ++c)
                    kt[kk][c] = sKT[(k0 + kk) * 65 + 4 * tc + c];
#pragma unroll
            for (int a = 0; a < 4; ++a)
#pragma unroll
                for (int c = 0; c < 4; ++c)
                    acc[a][c] += qv[a].x * kt[0][c] + qv[a].y * kt[1][c]
                               + qv[a].z * kt[2][c] + qv[a].w * kt[3][c];
        }

        const bool diag = (j == qi);
#pragma unroll
        for (int a = 0; a < 4; ++a)
#pragma unroll
            for (int c = 0; c < 4; ++c) {
                float sv = 50.f * tanhf(acc[a][c] * 0.02f);
                if (diag && (4 * tc + c > 4 * tr + a)) sv = -1e30f;
                sS[(4 * tr + a) * 65 + 4 * tc + c] = sv;
            }
        __syncthreads();

        // Online softmax update: 4 threads per row, 16 cols each
        float sv16[16];
        float tmax = -1e30f;
#pragma unroll
        for (int u = 0; u < 16; ++u) {
            sv16[u] = sS[r * 65 + qq * 16 + u];
            tmax = fmaxf(tmax, sv16[u]);
        }
        tmax = fmaxf(tmax, __shfl_xor_sync(0xffffffffu, tmax, 1));
        tmax = fmaxf(tmax, __shfl_xor_sync(0xffffffffu, tmax, 2));
        float mnew  = fmaxf(m, tmax);
        float scale = expf(m - mnew);
        float rsum  = 0.f;
#pragma unroll
        for (int u = 0; u < 16; ++u) {
            float p = expf(sv16[u] - mnew);
            rsum += p;
            sS[r * 65 + qq * 16 + u] = p;
        }
        rsum += __shfl_xor_sync(0xffffffffu, rsum, 1);
        rsum += __shfl_xor_sync(0xffffffffu, rsum, 2);
        l = l * scale + rsum;
        m = mnew;
#pragma unroll
        for (int u = 0; u < 8; ++u) {
            o[u].x *= scale; o[u].y *= scale; o[u].z *= scale; o[u].w *= scale;
        }
        __syncthreads();

        // O += P V  (thread owns row r, dims qq*32..qq*32+31)
#pragma unroll 4
        for (int jj = 0; jj < 64; ++jj) {
            float p = sS[r * 65 + jj];
#pragma unroll
            for (int u = 0; u < 8; ++u) {
                float4 vv = *(float4*)&sV[jj * 128 + qq * 32 + u * 4];
                fma4(o[u], p, vv);
            }
        }
    }

    float inv = 1.f / l;
#pragma unroll
    for (int u = 0; u < 8; ++u) {
        float4 ov = make_float4(o[u].x * inv, o[u].y * inv, o[u].z * inv, o[u].w * inv);
        *(float4*)&O[base + (size_t)(qi * 64 + r) * Dc + qq * 32 + u * 4] = ov;
    }
}

// ---------------------------------------------------------------------------
extern "C" void kernel_launch(void* const* d_in, const int* in_sizes, int n_in,
                              void* d_out, int out_size)
{
    const float* hidden = (const float*)d_in[0];
    const float* wq = (const float*)d_in[1];
    const float* wk = (const float*)d_in[2];
    const float* wv = (const float*)d_in[3];
    const float* wo = (const float*)d_in[4];
    float* out = (float*)d_out;

    float *q, *k, *v, *o;
    cudaGetSymbolAddress((void**)&q, g_q);
    cudaGetSymbolAddress((void**)&k, g_k);
    cudaGetSymbolAddress((void**)&v, g_v);
    cudaGetSymbolAddress((void**)&o, g_o);

    const int smem_bytes = FLASH_SMEM_FLOATS * (int)sizeof(float);  // 115456
    cudaFuncSetAttribute(flash_attn, cudaFuncAttributeMaxDynamicSharedMemorySize, smem_bytes);

    dim3 ggrid(2048 / 64, 4096 / 128);  // N tiles x M tiles
    gemm128x64<<<ggrid, 256>>>(hidden, wq, q);
    gemm128x64<<<ggrid, 256>>>(hidden, wk, k);
    gemm128x64<<<ggrid, 256>>>(hidden, wv, v);

    rotary_kernel<<<(Bc * Sc * Hc * 64) / 256, 256>>>(q, k);

    flash_attn<<<dim3(Sc / 64, Hc, Bc), 256, smem_bytes>>>(q, k, v, o);

    gemm128x64<<<ggrid, 256>>>(o, wo, out);
}

// round 6
// speedup vs baseline: 1.2309x; 1.2309x over previous
#include <cuda_runtime.h>
#include <cuda_bf16.h>
#include <cstdint>
#include <math.h>

// Problem dims
#define Bc  2
#define Sc  2048
#define Dc  2048
#define Hc  16
#define HDc 128
#define MTOT (Bc * Sc)            // 4096
#define TOTE (Bc * Sc * Dc)       // 8388608
#define DD   (Dc * Dc)            // 4194304

// ---------------------------------------------------------------------------
// Scratch (__device__ globals: allocation-free rule)
// ---------------------------------------------------------------------------
__device__ float g_q[TOTE];
__device__ float g_k[TOTE];
__device__ float g_v[TOTE];
__device__ float g_o[TOTE];
__device__ __nv_bfloat16 g_xhi[TOTE];      // split of activations (hidden, then o)
__device__ __nv_bfloat16 g_xlo[TOTE];
__device__ __nv_bfloat16 g_whiT[4 * DD];   // W^T splits for wq,wk,wv,wo  [n][k]
__device__ __nv_bfloat16 g_wloT[4 * DD];

// ---------------------------------------------------------------------------
// PTX helpers (baseline ISA: mma.sync / ldmatrix / cp.async — sm_103-safe)
// ---------------------------------------------------------------------------
__device__ __forceinline__ uint32_t smem_u32(const void* p) {
    uint32_t a;
    asm("{ .reg .u64 t; cvta.to.shared.u64 t, %1; cvt.u32.u64 %0, t; }" : "=r"(a) : "l"(p));
    return a;
}
__device__ __forceinline__ void ldsm4(uint32_t* r, uint32_t addr) {
    asm volatile("ldmatrix.sync.aligned.m8n8.x4.shared.b16 {%0,%1,%2,%3}, [%4];"
                 : "=r"(r[0]), "=r"(r[1]), "=r"(r[2]), "=r"(r[3]) : "r"(addr));
}
__device__ __forceinline__ void ldsm2(uint32_t* r, uint32_t addr) {
    asm volatile("ldmatrix.sync.aligned.m8n8.x2.shared.b16 {%0,%1}, [%2];"
                 : "=r"(r[0]), "=r"(r[1]) : "r"(addr));
}
__device__ __forceinline__ void mma16816(float* c, const uint32_t* a, const uint32_t* b) {
    asm volatile("mma.sync.aligned.m16n8k16.row.col.f32.bf16.bf16.f32 "
                 "{%0,%1,%2,%3}, {%4,%5,%6,%7}, {%8,%9}, {%0,%1,%2,%3};"
                 : "+f"(c[0]), "+f"(c[1]), "+f"(c[2]), "+f"(c[3])
                 : "r"(a[0]), "r"(a[1]), "r"(a[2]), "r"(a[3]), "r"(b[0]), "r"(b[1]));
}
__device__ __forceinline__ void cp16(uint32_t smem, const void* g) {
    asm volatile("cp.async.cg.shared.global [%0], [%1], 16;" :: "r"(smem), "l"(g));
}
#define CP_COMMIT() asm volatile("cp.async.commit_group;" ::: "memory")
#define CP_WAIT(N)  asm volatile("cp.async.wait_group %0;" :: "n"(N) : "memory")

// ---------------------------------------------------------------------------
// fp32 -> bf16 hi/lo split (elementwise, float4 vectorized)
// ---------------------------------------------------------------------------
__global__ void conv_split(const float* __restrict__ in,
                           __nv_bfloat16* __restrict__ hi,
                           __nv_bfloat16* __restrict__ lo, int n4)
{
    int i = blockIdx.x * blockDim.x + threadIdx.x;
    if (i >= n4) return;
    float4 v = ((const float4*)in)[i];
    __nv_bfloat16 h0 = __float2bfloat16(v.x);
    __nv_bfloat16 h1 = __float2bfloat16(v.y);
    __nv_bfloat16 h2 = __float2bfloat16(v.z);
    __nv_bfloat16 h3 = __float2bfloat16(v.w);
    __nv_bfloat16 l0 = __float2bfloat16(v.x - __bfloat162float(h0));
    __nv_bfloat16 l1 = __float2bfloat16(v.y - __bfloat162float(h1));
    __nv_bfloat16 l2 = __float2bfloat16(v.z - __bfloat162float(h2));
    __nv_bfloat16 l3 = __float2bfloat16(v.w - __bfloat162float(h3));
    __nv_bfloat162* hp = (__nv_bfloat162*)hi;
    __nv_bfloat162* lp = (__nv_bfloat162*)lo;
    hp[2 * i]     = __nv_bfloat162(h0, h1);
    hp[2 * i + 1] = __nv_bfloat162(h2, h3);
    lp[2 * i]     = __nv_bfloat162(l0, l1);
    lp[2 * i + 1] = __nv_bfloat162(l2, l3);
}

// ---------------------------------------------------------------------------
// W[k][n] fp32 -> W^T[n][k] bf16 hi/lo, tiled transpose
// ---------------------------------------------------------------------------
__global__ void conv_w_t(const float* __restrict__ w,
                         __nv_bfloat16* __restrict__ hiT,
                         __nv_bfloat16* __restrict__ loT)
{
    __shared__ float tile[32][33];
    int n0 = blockIdx.x * 32, k0 = blockIdx.y * 32;
    int tx = threadIdx.x, ty = threadIdx.y;   // 32 x 8
#pragma unroll
    for (int i = 0; i < 4; ++i)
        tile[ty + i * 8][tx] = w[(size_t)(k0 + ty + i * 8) * Dc + n0 + tx];
    __syncthreads();
#pragma unroll
    for (int i = 0; i < 4; ++i) {
        float v = tile[tx][ty + i * 8];
        __nv_bfloat16 h = __float2bfloat16(v);
        __nv_bfloat16 l = __float2bfloat16(v - __bfloat162float(h));
        size_t oidx = (size_t)(n0 + ty + i * 8) * Dc + k0 + tx;
        hiT[oidx] = h;
        loT[oidx] = l;
    }
}

// ---------------------------------------------------------------------------
// HMMA bf16 3-split GEMM: C[4096x2048] = A @ W
//   A given as hi/lo bf16 [m][k]; W given as hi/lo bf16 transposed [n][k].
//   CTA: 128x128, 8 warps (2x4), warp tile 64x32, K-tile 32, 2-stage cp.async.
// Smem tile: 128 rows x 40 bf16 (80 B stride: 16B-aligned, ldmatrix
// conflict-free since row*20 mod 32 banks are distinct within 8 rows).
// ---------------------------------------------------------------------------
#define GKT 32
#define ROWB 80                          // bytes per smem row (32 bf16 + 8 pad)
#define TILE_B (128 * ROWB)              // 10240 B per tile
#define STAGE_B (4 * TILE_B)             // Ahi, Alo, Bhi, Blo
#define GSMEM_TOTAL (2 * STAGE_B)        // 81920

__global__ __launch_bounds__(256) void gemm_hmma(
    const __nv_bfloat16* __restrict__ Ahi, const __nv_bfloat16* __restrict__ Alo,
    const __nv_bfloat16* __restrict__ BhiT, const __nv_bfloat16* __restrict__ BloT,
    float* __restrict__ C)
{
    extern __shared__ __align__(128) char smem[];
    const uint32_t sb = smem_u32(smem);
    const int t   = threadIdx.x;
    const int l   = t & 31;
    const int wid = t >> 5;
    const int wm  = wid >> 2;           // 0..1 -> m offset wm*64
    const int wn  = wid & 3;            // 0..3 -> n offset wn*32
    const int m0  = blockIdx.y * 128;
    const int n0  = blockIdx.x * 128;

    // ldmatrix per-lane address offsets (bytes, within a tile)
    const int arow = (l & 7) + ((l >> 3) & 1) * 8;
    const int ak8  = (l >> 4);                     // 0/1 -> +8 bf16
    const uint32_t aoff = (uint32_t)((wm * 64 + arow) * ROWB + ak8 * 16);
    const int brow = l & 7;
    const int bk8  = (l >> 3) & 1;
    const uint32_t boff = (uint32_t)((wn * 32 + brow) * ROWB + bk8 * 16);

    // cp.async load descriptors: per tile 512 chunks of 16B, 2 per thread
    const int r0c = (t * 2) >> 2, c0c = (t * 2) & 3;          // chunk 2t
    const int r1c = (t * 2 + 1) >> 2, c1c = (t * 2 + 1) & 3;  // chunk 2t+1

    float acc[4][4][4];
#pragma unroll
    for (int i = 0; i < 4; ++i)
#pragma unroll
        for (int j = 0; j < 4; ++j)
#pragma unroll
            for (int u = 0; u < 4; ++u) acc[i][j][u] = 0.f;

    const __nv_bfloat16* srcs[4] = {Ahi, Alo, BhiT, BloT};

    // ---- load ktile into stage s ----
    auto load_tiles = [&](int kt, int s) {
        const uint32_t st = sb + s * STAGE_B;
#pragma unroll
        for (int tl = 0; tl < 4; ++tl) {
            const __nv_bfloat16* src = srcs[tl];
            const int rbase = (tl < 2) ? m0 : n0;
            cp16(st + tl * TILE_B + r0c * ROWB + c0c * 16,
                 src + (size_t)(rbase + r0c) * Dc + kt * GKT + c0c * 8);
            cp16(st + tl * TILE_B + r1c * ROWB + c1c * 16,
                 src + (size_t)(rbase + r1c) * Dc + kt * GKT + c1c * 8);
        }
    };

    load_tiles(0, 0);
    CP_COMMIT();

    for (int kt = 0; kt < Dc / GKT; ++kt) {
        if (kt + 1 < Dc / GKT) {
            load_tiles(kt + 1, (kt + 1) & 1);
            CP_COMMIT();
            CP_WAIT(1);
        } else {
            CP_WAIT(0);
        }
        __syncthreads();

        const uint32_t st = sb + (kt & 1) * STAGE_B;
        const uint32_t aHi = st + 0 * TILE_B + aoff;
        const uint32_t aLo = st + 1 * TILE_B + aoff;
        const uint32_t bHi = st + 2 * TILE_B + boff;
        const uint32_t bLo = st + 3 * TILE_B + boff;

#pragma unroll
        for (int ks = 0; ks < 2; ++ks) {
            uint32_t ah[4][4], al[4][4], bh[4][2], bl[4][2];
#pragma unroll
            for (int mt = 0; mt < 4; ++mt) {
                ldsm4(ah[mt], aHi + mt * (16 * ROWB) + ks * 32);
                ldsm4(al[mt], aLo + mt * (16 * ROWB) + ks * 32);
            }
#pragma unroll
            for (int nt = 0; nt < 4; ++nt) {
                ldsm2(bh[nt], bHi + nt * (8 * ROWB) + ks * 32);
                ldsm2(bl[nt], bLo + nt * (8 * ROWB) + ks * 32);
            }
#pragma unroll
            for (int mt = 0; mt < 4; ++mt)
#pragma unroll
                for (int nt = 0; nt < 4; ++nt)
                    mma16816(acc[mt][nt], ah[mt], bh[nt]);
#pragma unroll
            for (int mt = 0; mt < 4; ++mt)
#pragma unroll
                for (int nt = 0; nt < 4; ++nt)
                    mma16816(acc[mt][nt], ah[mt], bl[nt]);
#pragma unroll
            for (int mt = 0; mt < 4; ++mt)
#pragma unroll
                for (int nt = 0; nt < 4; ++nt)
                    mma16816(acc[mt][nt], al[mt], bh[nt]);
        }
        __syncthreads();
    }

    // Epilogue: fragment (row l/4 [+8], col 2*(l%4)) -> float2 stores
    const int erow = m0 + wm * 64 + (l >> 2);
    const int ecol = n0 + wn * 32 + (l & 3) * 2;
#pragma unroll
    for (int mt = 0; mt < 4; ++mt)
#pragma unroll
        for (int nt = 0; nt < 4; ++nt) {
            *(float2*)&C[(size_t)(erow + mt * 16) * Dc + ecol + nt * 8] =
                make_float2(acc[mt][nt][0], acc[mt][nt][1]);
            *(float2*)&C[(size_t)(erow + mt * 16 + 8) * Dc + ecol + nt * 8] =
                make_float2(acc[mt][nt][2], acc[mt][nt][3]);
        }
}

// ---------------------------------------------------------------------------
// Rotary (unchanged)
// ---------------------------------------------------------------------------
__global__ void rotary_kernel(float* __restrict__ q, float* __restrict__ k)
{
    int idx = blockIdx.x * blockDim.x + threadIdx.x;
    if (idx >= Bc * Sc * Hc * 64) return;
    int j = idx & 63;
    int h = (idx >> 6) & (Hc - 1);
    int s = (idx >> 10) & (Sc - 1);
    int b = idx >> 21;

    float fraction = (float)j * (1.0f / 64.0f);
    float inv_freq = 1.0f / powf(10000.0f, fraction);
    float ang = (float)s * inv_freq;
    float sn, cs;
    sincosf(ang, &sn, &cs);

    size_t base = ((size_t)(b * Sc + s)) * Dc + h * HDc + j;
    float q1 = q[base], q2 = q[base + 64];
    q[base]      = q1 * cs - q2 * sn;
    q[base + 64] = q2 * cs + q1 * sn;
    float k1 = k[base], k2 = k[base + 64];
    k[base]      = k1 * cs - k2 * sn;
    k[base + 64] = k2 * cs + k1 * sn;
}

// ---------------------------------------------------------------------------
// Flash attention (unchanged from R2): causal, tanh cap, Lingvo softmax
// ---------------------------------------------------------------------------
__device__ __forceinline__ void fma4(float4& o, float s, const float4& b) {
    o.x += s * b.x; o.y += s * b.y; o.z += s * b.z; o.w += s * b.w;
}

#define FLASH_SMEM_FLOATS (64*128 + 128*65 + 64*128 + 64*65)

__global__ __launch_bounds__(256) void flash_attn(
    const float* __restrict__ Q, const float* __restrict__ K,
    const float* __restrict__ V, float* __restrict__ O)
{
    extern __shared__ float sm[];
    float* sQ  = sm;
    float* sKT = sm + 64 * 128;
    float* sV  = sKT + 128 * 65;
    float* sS  = sV + 64 * 128;

    const int t  = threadIdx.x;
    const int qi = blockIdx.x;
    const int h  = blockIdx.y;
    const int b  = blockIdx.z;
    const size_t base = (size_t)b * Sc * Dc + (size_t)h * HDc;

#pragma unroll
    for (int it = 0; it < 8; ++it) {
        int f = it * 256 + t;
        int row = f >> 5, dc = f & 31;
        float4 v4 = *(const float4*)&Q[base + (size_t)(qi * 64 + row) * Dc + dc * 4];
        *(float4*)&sQ[row * 128 + dc * 4] = v4;
    }

    float m = 0.f, l = 1.f;
    float4 o[8];
#pragma unroll
    for (int u = 0; u < 8; ++u) o[u] = make_float4(0.f, 0.f, 0.f, 0.f);

    const int r  = t >> 2;
    const int qq = t & 3;
    const int tr = t >> 4, tc = t & 15;

    for (int j = 0; j <= qi; ++j) {
        __syncthreads();
#pragma unroll
        for (int it = 0; it < 8; ++it) {
            int f = it * 256 + t;
            int wIdx = f >> 5;
            int half = wIdx & 1;
            int rb   = (wIdx >> 1) << 1;
            int ln   = f & 31;
            int srow = rb + (ln >> 4);
            int dc   = half * 16 + (ln & 15);
            float4 kv = *(const float4*)&K[base + (size_t)(j * 64 + srow) * Dc + dc * 4];
            sKT[(dc * 4 + 0) * 65 + srow] = kv.x;
            sKT[(dc * 4 + 1) * 65 + srow] = kv.y;
            sKT[(dc * 4 + 2) * 65 + srow] = kv.z;
            sKT[(dc * 4 + 3) * 65 + srow] = kv.w;

            int rowv = f >> 5, dcv = f & 31;
            float4 vv = *(const float4*)&V[base + (size_t)(j * 64 + rowv) * Dc + dcv * 4];
            *(float4*)&sV[rowv * 128 + dcv * 4] = vv;
        }
        __syncthreads();

        float acc[4][4];
#pragma unroll
        for (int a = 0; a < 4; ++a)
#pragma unroll
            for (int c = 0; c < 4; ++c) acc[a][c] = 0.f;

#pragma unroll 4
        for (int k0 = 0; k0 < 128; k0 += 4) {
            float4 qv[4];
#pragma unroll
            for (int a = 0; a < 4; ++a)
                qv[a] = *(float4*)&sQ[(4 * tr + a) * 128 + k0];
            float kt[4][4];
#pragma unroll
            for (int kk = 0; kk < 4; ++kk)
#pragma unroll
                for (int c = 0; c < 4; ++c)
                    kt[kk][c] = sKT[(k0 + kk) * 65 + 4 * tc + c];
#pragma unroll
            for (int a = 0; a < 4; ++a)
#pragma unroll
                for (int c = 0; c < 4; ++c)
                    acc[a][c] += qv[a].x * kt[0][c] + qv[a].y * kt[1][c]
                               + qv[a].z * kt[2][c] + qv[a].w * kt[3][c];
        }

        const bool diag = (j == qi);
#pragma unroll
        for (int a = 0; a < 4; ++a)
#pragma unroll
            for (int c = 0; c < 4; ++c) {
                float sv = 50.f * tanhf(acc[a][c] * 0.02f);
                if (diag && (4 * tc + c > 4 * tr + a)) sv = -1e30f;
                sS[(4 * tr + a) * 65 + 4 * tc + c] = sv;
            }
        __syncthreads();

        float sv16[16];
        float tmax = -1e30f;
#pragma unroll
        for (int u = 0; u < 16; ++u) {
            sv16[u] = sS[r * 65 + qq * 16 + u];
            tmax = fmaxf(tmax, sv16[u]);
        }
        tmax = fmaxf(tmax, __shfl_xor_sync(0xffffffffu, tmax, 1));
        tmax = fmaxf(tmax, __shfl_xor_sync(0xffffffffu, tmax, 2));
        float mnew  = fmaxf(m, tmax);
        float scale = expf(m - mnew);
        float rsum  = 0.f;
#pragma unroll
        for (int u = 0; u < 16; ++u) {
            float p = expf(sv16[u] - mnew);
            rsum += p;
            sS[r * 65 + qq * 16 + u] = p;
        }
        rsum += __shfl_xor_sync(0xffffffffu, rsum, 1);
        rsum += __shfl_xor_sync(0xffffffffu, rsum, 2);
        l = l * scale + rsum;
        m = mnew;
#pragma unroll
        for (int u = 0; u < 8; ++u) {
            o[u].x *= scale; o[u].y *= scale; o[u].z *= scale; o[u].w *= scale;
        }
        __syncthreads();

#pragma unroll 4
        for (int jj = 0; jj < 64; ++jj) {
            float p = sS[r * 65 + jj];
#pragma unroll
            for (int u = 0; u < 8; ++u) {
                float4 vv = *(float4*)&sV[jj * 128 + qq * 32 + u * 4];
                fma4(o[u], p, vv);
            }
        }
    }

    float inv = 1.f / l;
#pragma unroll
    for (int u = 0; u < 8; ++u) {
        float4 ov = make_float4(o[u].x * inv, o[u].y * inv, o[u].z * inv, o[u].w * inv);
        *(float4*)&O[base + (size_t)(qi * 64 + r) * Dc + qq * 32 + u * 4] = ov;
    }
}

// ---------------------------------------------------------------------------
extern "C" void kernel_launch(void* const* d_in, const int* in_sizes, int n_in,
                              void* d_out, int out_size)
{
    const float* hidden = (const float*)d_in[0];
    const float* wq = (const float*)d_in[1];
    const float* wk = (const float*)d_in[2];
    const float* wv = (const float*)d_in[3];
    const float* wo = (const float*)d_in[4];
    float* out = (float*)d_out;

    float *q, *k, *v, *o;
    __nv_bfloat16 *xhi, *xlo, *whiT, *wloT;
    cudaGetSymbolAddress((void**)&q, g_q);
    cudaGetSymbolAddress((void**)&k, g_k);
    cudaGetSymbolAddress((void**)&v, g_v);
    cudaGetSymbolAddress((void**)&o, g_o);
    cudaGetSymbolAddress((void**)&xhi, g_xhi);
    cudaGetSymbolAddress((void**)&xlo, g_xlo);
    cudaGetSymbolAddress((void**)&whiT, g_whiT);
    cudaGetSymbolAddress((void**)&wloT, g_wloT);

    const int flash_smem = FLASH_SMEM_FLOATS * (int)sizeof(float);
    cudaFuncSetAttribute(flash_attn, cudaFuncAttributeMaxDynamicSharedMemorySize, flash_smem);
    cudaFuncSetAttribute(gemm_hmma, cudaFuncAttributeMaxDynamicSharedMemorySize, GSMEM_TOTAL);

    // 1. split activations + weights to bf16 hi/lo (W also transposed)
    conv_split<<<(TOTE / 4 + 255) / 256, 256>>>(hidden, xhi, xlo, TOTE / 4);
    dim3 wgrid(Dc / 32, Dc / 32), wblk(32, 8);
    conv_w_t<<<wgrid, wblk>>>(wq, whiT + 0 * DD, wloT + 0 * DD);
    conv_w_t<<<wgrid, wblk>>>(wk, whiT + 1 * DD, wloT + 1 * DD);
    conv_w_t<<<wgrid, wblk>>>(wv, whiT + 2 * DD, wloT + 2 * DD);
    conv_w_t<<<wgrid, wblk>>>(wo, whiT + 3 * DD, wloT + 3 * DD);

    // 2. QKV projections on tensor cores (HMMA)
    dim3 ggrid(Dc / 128, MTOT / 128);   // (16, 32)
    gemm_hmma<<<ggrid, 256, GSMEM_TOTAL>>>(xhi, xlo, whiT + 0 * DD, wloT + 0 * DD, q);
    gemm_hmma<<<ggrid, 256, GSMEM_TOTAL>>>(xhi, xlo, whiT + 1 * DD, wloT + 1 * DD, k);
    gemm_hmma<<<ggrid, 256, GSMEM_TOTAL>>>(xhi, xlo, whiT + 2 * DD, wloT + 2 * DD, v);

    // 3. rotary + attention
    rotary_kernel<<<(Bc * Sc * Hc * 64) / 256, 256>>>(q, k);
    flash_attn<<<dim3(Sc / 64, Hc, Bc), 256, flash_smem>>>(q, k, v, o);

    // 4. output projection
    conv_split<<<(TOTE / 4 + 255) / 256, 256>>>(o, xhi, xlo, TOTE / 4);
    gemm_hmma<<<ggrid, 256, GSMEM_TOTAL>>>(xhi, xlo, whiT + 3 * DD, wloT + 3 * DD, out);
}

// round 8
// speedup vs baseline: 4.3449x; 3.5298x over previous
#include <cuda_runtime.h>
#include <cuda_bf16.h>
#include <cstdint>
#include <math.h>

// Problem dims
#define Bc  2
#define Sc  2048
#define Dc  2048
#define Hc  16
#define HDc 128
#define MTOT (Bc * Sc)            // 4096
#define TOTE (Bc * Sc * Dc)       // 8388608
#define DD   (Dc * Dc)            // 4194304

// ---------------------------------------------------------------------------
// Scratch (__device__ globals: allocation-free rule)
// ---------------------------------------------------------------------------
__device__ float g_q[TOTE];
__device__ float g_k[TOTE];
__device__ float g_v[TOTE];
__device__ __nv_bfloat16 g_xhi[TOTE];      // GEMM activation splits
__device__ __nv_bfloat16 g_xlo[TOTE];
__device__ __nv_bfloat16 g_whiT[4 * DD];   // W^T splits for wq,wk,wv,wo  [n][k]
__device__ __nv_bfloat16 g_wloT[4 * DD];
// attention operands, [b][h][s][128] layout
__device__ __nv_bfloat16 g_qhi[TOTE], g_qlo[TOTE];
__device__ __nv_bfloat16 g_khi[TOTE], g_klo[TOTE];
__device__ __nv_bfloat16 g_vhi[TOTE], g_vlo[TOTE];

// ---------------------------------------------------------------------------
// PTX helpers (baseline ISA: mma.sync / ldmatrix / cp.async — sm_103-safe)
// ---------------------------------------------------------------------------
__device__ __forceinline__ uint32_t smem_u32(const void* p) {
    uint32_t a;
    asm("{ .reg .u64 t; cvta.to.shared.u64 t, %1; cvt.u32.u64 %0, t; }" : "=r"(a) : "l"(p));
    return a;
}
__device__ __forceinline__ void ldsm4(uint32_t* r, uint32_t addr) {
    asm volatile("ldmatrix.sync.aligned.m8n8.x4.shared.b16 {%0,%1,%2,%3}, [%4];"
                 : "=r"(r[0]), "=r"(r[1]), "=r"(r[2]), "=r"(r[3]) : "r"(addr));
}
__device__ __forceinline__ void ldsm2(uint32_t* r, uint32_t addr) {
    asm volatile("ldmatrix.sync.aligned.m8n8.x2.shared.b16 {%0,%1}, [%2];"
                 : "=r"(r[0]), "=r"(r[1]) : "r"(addr));
}
__device__ __forceinline__ void ldsm2t(uint32_t* r, uint32_t addr) {
    asm volatile("ldmatrix.sync.aligned.m8n8.x2.trans.shared.b16 {%0,%1}, [%2];"
                 : "=r"(r[0]), "=r"(r[1]) : "r"(addr));
}
__device__ __forceinline__ void mma16816(float* c, const uint32_t* a, const uint32_t* b) {
    asm volatile("mma.sync.aligned.m16n8k16.row.col.f32.bf16.bf16.f32 "
                 "{%0,%1,%2,%3}, {%4,%5,%6,%7}, {%8,%9}, {%0,%1,%2,%3};"
                 : "+f"(c[0]), "+f"(c[1]), "+f"(c[2]), "+f"(c[3])
                 : "r"(a[0]), "r"(a[1]), "r"(a[2]), "r"(a[3]), "r"(b[0]), "r"(b[1]));
}
__device__ __forceinline__ void cp16(uint32_t smem, const void* g) {
    asm volatile("cp.async.cg.shared.global [%0], [%1], 16;" :: "r"(smem), "l"(g));
}
#define CP_COMMIT() asm volatile("cp.async.commit_group;" ::: "memory")
#define CP_WAIT(N)  asm volatile("cp.async.wait_group %0;" :: "n"(N) : "memory")

__device__ __forceinline__ void splitpack(float x, float y, uint32_t& hi, uint32_t& lo) {
    __nv_bfloat16 hx = __float2bfloat16(x), hy = __float2bfloat16(y);
    float lx = x - __bfloat162float(hx), ly = y - __bfloat162float(hy);
    __nv_bfloat162 hv(hx, hy);
    __nv_bfloat162 lv(__float2bfloat16(lx), __float2bfloat16(ly));
    hi = *(uint32_t*)&hv;
    lo = *(uint32_t*)&lv;
}

// ---------------------------------------------------------------------------
// fp32 -> bf16 hi/lo split (elementwise, float4 vectorized)
// ---------------------------------------------------------------------------
__global__ void conv_split(const float* __restrict__ in,
                           __nv_bfloat16* __restrict__ hi,
                           __nv_bfloat16* __restrict__ lo, int n4)
{
    int i = blockIdx.x * blockDim.x + threadIdx.x;
    if (i >= n4) return;
    float4 v = ((const float4*)in)[i];
    uint32_t h0, l0, h1, l1;
    splitpack(v.x, v.y, h0, l0);
    splitpack(v.z, v.w, h1, l1);
    uint32_t* hp = (uint32_t*)hi;
    uint32_t* lp = (uint32_t*)lo;
    hp[2 * i] = h0; hp[2 * i + 1] = h1;
    lp[2 * i] = l0; lp[2 * i + 1] = l1;
}

// ---------------------------------------------------------------------------
// W[k][n] fp32 -> W^T[n][k] bf16 hi/lo, tiled transpose
// ---------------------------------------------------------------------------
__global__ void conv_w_t(const float* __restrict__ w,
                         __nv_bfloat16* __restrict__ hiT,
                         __nv_bfloat16* __restrict__ loT)
{
    __shared__ float tile[32][33];
    int n0 = blockIdx.x * 32, k0 = blockIdx.y * 32;
    int tx = threadIdx.x, ty = threadIdx.y;   // 32 x 8
#pragma unroll
    for (int i = 0; i < 4; ++i)
        tile[ty + i * 8][tx] = w[(size_t)(k0 + ty + i * 8) * Dc + n0 + tx];
    __syncthreads();
#pragma unroll
    for (int i = 0; i < 4; ++i) {
        float v = tile[tx][ty + i * 8];
        __nv_bfloat16 h = __float2bfloat16(v);
        __nv_bfloat16 l = __float2bfloat16(v - __bfloat162float(h));
        size_t oidx = (size_t)(n0 + ty + i * 8) * Dc + k0 + tx;
        hiT[oidx] = h;
        loT[oidx] = l;
    }
}

// ---------------------------------------------------------------------------
// HMMA bf16 3-split GEMM (validated R6): C[4096x2048] = A @ W
// ---------------------------------------------------------------------------
#define GKT 32
#define ROWB 80
#define TILE_B (128 * ROWB)
#define STAGE_B (4 * TILE_B)
#define GSMEM_TOTAL (2 * STAGE_B)        // 81920

__global__ __launch_bounds__(256) void gemm_hmma(
    const __nv_bfloat16* __restrict__ Ahi, const __nv_bfloat16* __restrict__ Alo,
    const __nv_bfloat16* __restrict__ BhiT, const __nv_bfloat16* __restrict__ BloT,
    float* __restrict__ C)
{
    extern __shared__ __align__(128) char smem[];
    const uint32_t sb = smem_u32(smem);
    const int t   = threadIdx.x;
    const int l   = t & 31;
    const int wid = t >> 5;
    const int wm  = wid >> 2;
    const int wn  = wid & 3;
    const int m0  = blockIdx.y * 128;
    const int n0  = blockIdx.x * 128;

    const int arow = (l & 7) + ((l >> 3) & 1) * 8;
    const int ak8  = (l >> 4);
    const uint32_t aoff = (uint32_t)((wm * 64 + arow) * ROWB + ak8 * 16);
    const int brow = l & 7;
    const int bk8  = (l >> 3) & 1;
    const uint32_t boff = (uint32_t)((wn * 32 + brow) * ROWB + bk8 * 16);

    const int r0c = (t * 2) >> 2, c0c = (t * 2) & 3;
    const int r1c = (t * 2 + 1) >> 2, c1c = (t * 2 + 1) & 3;

    float acc[4][4][4];
#pragma unroll
    for (int i = 0; i < 4; ++i)
#pragma unroll
        for (int j = 0; j < 4; ++j)
#pragma unroll
            for (int u = 0; u < 4; ++u) acc[i][j][u] = 0.f;

    const __nv_bfloat16* srcs[4] = {Ahi, Alo, BhiT, BloT};

    auto load_tiles = [&](int kt, int s) {
        const uint32_t st = sb + s * STAGE_B;
#pragma unroll
        for (int tl = 0; tl < 4; ++tl) {
            const __nv_bfloat16* src = srcs[tl];
            const int rbase = (tl < 2) ? m0 : n0;
            cp16(st + tl * TILE_B + r0c * ROWB + c0c * 16,
                 src + (size_t)(rbase + r0c) * Dc + kt * GKT + c0c * 8);
            cp16(st + tl * TILE_B + r1c * ROWB + c1c * 16,
                 src + (size_t)(rbase + r1c) * Dc + kt * GKT + c1c * 8);
        }
    };

    load_tiles(0, 0);
    CP_COMMIT();

    for (int kt = 0; kt < Dc / GKT; ++kt) {
        if (kt + 1 < Dc / GKT) {
            load_tiles(kt + 1, (kt + 1) & 1);
            CP_COMMIT();
            CP_WAIT(1);
        } else {
            CP_WAIT(0);
        }
        __syncthreads();

        const uint32_t st = sb + (kt & 1) * STAGE_B;
        const uint32_t aHi = st + 0 * TILE_B + aoff;
        const uint32_t aLo = st + 1 * TILE_B + aoff;
        const uint32_t bHi = st + 2 * TILE_B + boff;
        const uint32_t bLo = st + 3 * TILE_B + boff;

#pragma unroll
        for (int ks = 0; ks < 2; ++ks) {
            uint32_t ah[4][4], al[4][4], bh[4][2], bl[4][2];
#pragma unroll
            for (int mt = 0; mt < 4; ++mt) {
                ldsm4(ah[mt], aHi + mt * (16 * ROWB) + ks * 32);
                ldsm4(al[mt], aLo + mt * (16 * ROWB) + ks * 32);
            }
#pragma unroll
            for (int nt = 0; nt < 4; ++nt) {
                ldsm2(bh[nt], bHi + nt * (8 * ROWB) + ks * 32);
                ldsm2(bl[nt], bLo + nt * (8 * ROWB) + ks * 32);
            }
#pragma unroll
            for (int mt = 0; mt < 4; ++mt)
#pragma unroll
                for (int nt = 0; nt < 4; ++nt)
                    mma16816(acc[mt][nt], ah[mt], bh[nt]);
#pragma unroll
            for (int mt = 0; mt < 4; ++mt)
#pragma unroll
                for (int nt = 0; nt < 4; ++nt)
                    mma16816(acc[mt][nt], ah[mt], bl[nt]);
#pragma unroll
            for (int mt = 0; mt < 4; ++mt)
#pragma unroll
                for (int nt = 0; nt < 4; ++nt)
                    mma16816(acc[mt][nt], al[mt], bh[nt]);
        }
        __syncthreads();
    }

    const int erow = m0 + wm * 64 + (l >> 2);
    const int ecol = n0 + wn * 32 + (l & 3) * 2;
#pragma unroll
    for (int mt = 0; mt < 4; ++mt)
#pragma unroll
        for (int nt = 0; nt < 4; ++nt) {
            *(float2*)&C[(size_t)(erow + mt * 16) * Dc + ecol + nt * 8] =
                make_float2(acc[mt][nt][0], acc[mt][nt][1]);
            *(float2*)&C[(size_t)(erow + mt * 16 + 8) * Dc + ecol + nt * 8] =
                make_float2(acc[mt][nt][2], acc[mt][nt][3]);
        }
}

// ---------------------------------------------------------------------------
// Rotary + bf16 hi/lo split: fp32 [b][s][h*128+d] -> bf16 [b][h][s][128]
// ---------------------------------------------------------------------------
__global__ void rotary_split(const float* __restrict__ q, const float* __restrict__ k,
                             __nv_bfloat16* __restrict__ qhi, __nv_bfloat16* __restrict__ qlo,
                             __nv_bfloat16* __restrict__ khi, __nv_bfloat16* __restrict__ klo)
{
    int idx = blockIdx.x * blockDim.x + threadIdx.x;
    if (idx >= Bc * Sc * Hc * 64) return;
    int j = idx & 63;
    int h = (idx >> 6) & (Hc - 1);
    int s = (idx >> 10) & (Sc - 1);
    int b = idx >> 21;

    float inv_freq = 1.0f / powf(10000.0f, (float)j * (1.0f / 64.0f));
    float sn, cs;
    sincosf((float)s * inv_freq, &sn, &cs);

    size_t ib = ((size_t)(b * Sc + s)) * Dc + h * HDc + j;
    size_t ob = ((size_t)((b * Hc + h) * Sc + s)) * HDc + j;

    float q1 = q[ib], q2 = q[ib + 64];
    float qa = q1 * cs - q2 * sn;
    float qb = q2 * cs + q1 * sn;
    float k1 = k[ib], k2 = k[ib + 64];
    float ka = k1 * cs - k2 * sn;
    float kb = k2 * cs + k1 * sn;

    __nv_bfloat16 hqa = __float2bfloat16(qa), hqb = __float2bfloat16(qb);
    __nv_bfloat16 hka = __float2bfloat16(ka), hkb = __float2bfloat16(kb);
    qhi[ob] = hqa;      qhi[ob + 64] = hqb;
    qlo[ob] = __float2bfloat16(qa - __bfloat162float(hqa));
    qlo[ob + 64] = __float2bfloat16(qb - __bfloat162float(hqb));
    khi[ob] = hka;      khi[ob + 64] = hkb;
    klo[ob] = __float2bfloat16(ka - __bfloat162float(hka));
    klo[ob + 64] = __float2bfloat16(kb - __bfloat162float(hkb));
}

// ---------------------------------------------------------------------------
// V split: fp32 [b][s][h*128+d] -> bf16 hi/lo [b][h][s][128]
// ---------------------------------------------------------------------------
__global__ void v_split(const float* __restrict__ v,
                        __nv_bfloat16* __restrict__ vhi, __nv_bfloat16* __restrict__ vlo)
{
    int idx = blockIdx.x * blockDim.x + threadIdx.x;
    if (idx >= TOTE / 2) return;
    int d2 = idx & 63;
    int h = (idx >> 6) & (Hc - 1);
    int s = (idx >> 10) & (Sc - 1);
    int b = idx >> 21;
    const float2 vv = *(const float2*)&v[((size_t)(b * Sc + s)) * Dc + h * HDc + d2 * 2];
    uint32_t hp, lp;
    splitpack(vv.x, vv.y, hp, lp);
    size_t ob = ((size_t)((b * Hc + h) * Sc + s)) * HDc + d2 * 2;
    *(uint32_t*)&vhi[ob] = hp;
    *(uint32_t*)&vlo[ob] = lp;
}

// ---------------------------------------------------------------------------
// Flash attention on HMMA (3-split QK and PV), causal + tanh cap + Lingvo
// softmax (phantom 0-logit: init m=0, l=1).
// CTA: 128 q rows x KV tiles of 64; 8 warps; 2-stage cp.async K/V.
// Writes output-projection inputs (bf16 hi/lo) directly.
// ---------------------------------------------------------------------------
#define FSM_Q   0
#define FSM_ST  65536                    // stages start
#define FSM_TOT (65536 + 2 * 65536)      // 196608 = 192KB

__global__ __launch_bounds__(256) void flash_mma(
    const __nv_bfloat16* __restrict__ qhi, const __nv_bfloat16* __restrict__ qlo,
    const __nv_bfloat16* __restrict__ khi, const __nv_bfloat16* __restrict__ klo,
    const __nv_bfloat16* __restrict__ vhi, const __nv_bfloat16* __restrict__ vlo,
    __nv_bfloat16* __restrict__ Ohi, __nv_bfloat16* __restrict__ Olo)
{
    extern __shared__ __align__(128) char smem[];
    const uint32_t sb = smem_u32(smem);
    const int t = threadIdx.x, l = t & 31, w = t >> 5;
    const int qi = (Sc / 128 - 1) - blockIdx.x;        // heavy CTAs first
    const int h = blockIdx.y, b = blockIdx.z;
    const size_t hb = (size_t)(b * Hc + h) * Sc * HDc;

    // --- load Q tile (both splits), swizzled rows of 256B ---
#pragma unroll
    for (int i = 0; i < 8; ++i) {
        int c = t + 256 * i;                 // 0..2047 chunks of 16B
        int row = c >> 4, c16 = c & 15;
        uint32_t dst = (uint32_t)(row * 256 + ((c16 ^ (row & 7)) * 16));
        size_t src = hb + (size_t)(qi * 128 + row) * HDc + c16 * 8;
        cp16(sb + FSM_Q + dst, qhi + src);
        cp16(sb + FSM_Q + 32768 + dst, qlo + src);
    }
    auto load_kv = [&](int j, int st) {
        uint32_t stb = sb + FSM_ST + st * 65536;
#pragma unroll
        for (int i = 0; i < 4; ++i) {
            int c = t + 256 * i;             // 0..1023
            int row = c >> 4, c16 = c & 15;
            uint32_t dst = (uint32_t)(row * 256 + ((c16 ^ (row & 7)) * 16));
            size_t src = hb + (size_t)(j * 64 + row) * HDc + c16 * 8;
            cp16(stb + dst,         khi + src);
            cp16(stb + 16384 + dst, klo + src);
            cp16(stb + 32768 + dst, vhi + src);
            cp16(stb + 49152 + dst, vlo + src);
        }
    };
    load_kv(0, 0);
    CP_COMMIT();

    float accO[16][4];
#pragma unroll
    for (int n = 0; n < 16; ++n)
#pragma unroll
        for (int e = 0; e < 4; ++e) accO[n][e] = 0.f;
    float m0 = 0.f, m1 = 0.f, l0 = 1.f, l1 = 1.f;

    // ldmatrix address components
    const int aRow = 16 * w + (l & 15);
    const int aK8  = l >> 4;
    const int bRowL = l & 7;
    const int bK8   = (l >> 3) & 1;
    const int vRow0 = (l & 7) + 8 * ((l >> 3) & 1);

    const int nt = 2 * qi + 2;
    for (int j = 0; j < nt; ++j) {
        if (j + 1 < nt) {
            load_kv(j + 1, (j + 1) & 1);
            CP_COMMIT();
            CP_WAIT(1);
        } else {
            CP_WAIT(0);
        }
        __syncthreads();

        const uint32_t stb = sb + FSM_ST + (j & 1) * 65536;
        const uint32_t sKh = stb, sKl = stb + 16384;
        const uint32_t sVh = stb + 32768, sVl = stb + 49152;

        // ---- S = Q K^T (3-split) ----
        float accS[8][4];
#pragma unroll
        for (int n = 0; n < 8; ++n)
#pragma unroll
            for (int e = 0; e < 4; ++e) accS[n][e] = 0.f;

#pragma unroll
        for (int k = 0; k < 8; ++k) {
            uint32_t ah[4], al[4];
            int ac16 = 2 * k + aK8;
            uint32_t aoff = (uint32_t)(aRow * 256 + ((ac16 ^ (aRow & 7)) * 16));
            ldsm4(ah, sb + FSM_Q + aoff);
            ldsm4(al, sb + FSM_Q + 32768 + aoff);
#pragma unroll
            for (int n = 0; n < 8; ++n) {
                int brow = 8 * n + bRowL;
                int bc16 = 2 * k + bK8;
                uint32_t boff = (uint32_t)(brow * 256 + ((bc16 ^ (brow & 7)) * 16));
                uint32_t bh2[2], bl2[2];
                ldsm2(bh2, sKh + boff);
                ldsm2(bl2, sKl + boff);
                mma16816(accS[n], ah, bh2);
                mma16816(accS[n], ah, bl2);
                mma16816(accS[n], al, bh2);
            }
        }

        // ---- tanh cap + causal mask ----
#pragma unroll
        for (int n = 0; n < 8; ++n)
#pragma unroll
            for (int e = 0; e < 4; ++e)
                accS[n][e] = 50.f * tanhf(accS[n][e] * 0.02f);

        if (j >= 2 * qi) {
            int r0 = 16 * w + (l >> 2);
            int cb = j * 64 - qi * 128 + 2 * (l & 3);
#pragma unroll
            for (int n = 0; n < 8; ++n) {
                int c = cb + 8 * n;
                if (c     > r0)     accS[n][0] = -50.f;
                if (c + 1 > r0)     accS[n][1] = -50.f;
                if (c     > r0 + 8) accS[n][2] = -50.f;
                if (c + 1 > r0 + 8) accS[n][3] = -50.f;
            }
        }

        // ---- online softmax (rows r0 = e{0,1}, r1 = e{2,3}) ----
        float mx0 = -1e30f, mx1 = -1e30f;
#pragma unroll
        for (int n = 0; n < 8; ++n) {
            mx0 = fmaxf(mx0, fmaxf(accS[n][0], accS[n][1]));
            mx1 = fmaxf(mx1, fmaxf(accS[n][2], accS[n][3]));
        }
        mx0 = fmaxf(mx0, __shfl_xor_sync(0xffffffffu, mx0, 1));
        mx0 = fmaxf(mx0, __shfl_xor_sync(0xffffffffu, mx0, 2));
        mx1 = fmaxf(mx1, __shfl_xor_sync(0xffffffffu, mx1, 1));
        mx1 = fmaxf(mx1, __shfl_xor_sync(0xffffffffu, mx1, 2));
        float mn0 = fmaxf(m0, mx0), mn1 = fmaxf(m1, mx1);
        float sc0 = expf(m0 - mn0), sc1 = expf(m1 - mn1);
        float rs0 = 0.f, rs1 = 0.f;
#pragma unroll
        for (int n = 0; n < 8; ++n) {
            accS[n][0] = expf(accS[n][0] - mn0); rs0 += accS[n][0];
            accS[n][1] = expf(accS[n][1] - mn0); rs0 += accS[n][1];
            accS[n][2] = expf(accS[n][2] - mn1); rs1 += accS[n][2];
            accS[n][3] = expf(accS[n][3] - mn1); rs1 += accS[n][3];
        }
        rs0 += __shfl_xor_sync(0xffffffffu, rs0, 1);
        rs0 += __shfl_xor_sync(0xffffffffu, rs0, 2);
        rs1 += __shfl_xor_sync(0xffffffffu, rs1, 1);
        rs1 += __shfl_xor_sync(0xffffffffu, rs1, 2);
        l0 = l0 * sc0 + rs0;  m0 = mn0;
        l1 = l1 * sc1 + rs1;  m1 = mn1;
#pragma unroll
        for (int n = 0; n < 16; ++n) {
            accO[n][0] *= sc0; accO[n][1] *= sc0;
            accO[n][2] *= sc1; accO[n][3] *= sc1;
        }

        // ---- O += P V (3-split, P from accS fragments) ----
#pragma unroll
        for (int kk = 0; kk < 4; ++kk) {
            uint32_t pah[4], pal[4];
            splitpack(accS[2 * kk][0],     accS[2 * kk][1],     pah[0], pal[0]);
            splitpack(accS[2 * kk][2],     accS[2 * kk][3],     pah[1], pal[1]);
            splitpack(accS[2 * kk + 1][0], accS[2 * kk + 1][1], pah[2], pal[2]);
            splitpack(accS[2 * kk + 1][2], accS[2 * kk + 1][3], pah[3], pal[3]);
#pragma unroll
            for (int n = 0; n < 16; ++n) {
                int vrow = 16 * kk + vRow0;
                int vc16 = n ^ (vrow & 7);
                uint32_t voff = (uint32_t)(vrow * 256 + vc16 * 16);
                uint32_t vh2[2], vl2[2];
                ldsm2t(vh2, sVh + voff);
                ldsm2t(vl2, sVl + voff);
                mma16816(accO[n], pah, vh2);
                mma16816(accO[n], pah, vl2);
                mma16816(accO[n], pal, vh2);
            }
        }
        __syncthreads();
    }

    // ---- write O as bf16 hi/lo in [b][s][h*128+d] layout ----
    float i0 = 1.f / l0, i1 = 1.f / l1;
    int row0 = qi * 128 + 16 * w + (l >> 2);
    size_t ob0 = ((size_t)b * Sc + row0) * Dc + h * HDc;
    size_t ob1 = ob0 + 8 * (size_t)Dc;
#pragma unroll
    for (int n = 0; n < 16; ++n) {
        int d = 8 * n + 2 * (l & 3);
        uint32_t hp, lp;
        splitpack(accO[n][0] * i0, accO[n][1] * i0, hp, lp);
        *(uint32_t*)&Ohi[ob0 + d] = hp;
        *(uint32_t*)&Olo[ob0 + d] = lp;
        splitpack(accO[n][2] * i1, accO[n][3] * i1, hp, lp);
        *(uint32_t*)&Ohi[ob1 + d] = hp;
        *(uint32_t*)&Olo[ob1 + d] = lp;
    }
}

// ---------------------------------------------------------------------------
extern "C" void kernel_launch(void* const* d_in, const int* in_sizes, int n_in,
                              void* d_out, int out_size)
{
    const float* hidden = (const float*)d_in[0];
    const float* wq = (const float*)d_in[1];
    const float* wk = (const float*)d_in[2];
    const float* wv = (const float*)d_in[3];
    const float* wo = (const float*)d_in[4];
    float* out = (float*)d_out;

    float *q, *k, *v;
    __nv_bfloat16 *xhi, *xlo, *whiT, *wloT;
    __nv_bfloat16 *qhi, *qlo, *khi, *klo, *vhi, *vlo;
    cudaGetSymbolAddress((void**)&q, g_q);
    cudaGetSymbolAddress((void**)&k, g_k);
    cudaGetSymbolAddress((void**)&v, g_v);
    cudaGetSymbolAddress((void**)&xhi, g_xhi);
    cudaGetSymbolAddress((void**)&xlo, g_xlo);
    cudaGetSymbolAddress((void**)&whiT, g_whiT);
    cudaGetSymbolAddress((void**)&wloT, g_wloT);
    cudaGetSymbolAddress((void**)&qhi, g_qhi);
    cudaGetSymbolAddress((void**)&qlo, g_qlo);
    cudaGetSymbolAddress((void**)&khi, g_khi);
    cudaGetSymbolAddress((void**)&klo, g_klo);
    cudaGetSymbolAddress((void**)&vhi, g_vhi);
    cudaGetSymbolAddress((void**)&vlo, g_vlo);

    cudaFuncSetAttribute(gemm_hmma, cudaFuncAttributeMaxDynamicSharedMemorySize, GSMEM_TOTAL);
    cudaFuncSetAttribute(flash_mma, cudaFuncAttributeMaxDynamicSharedMemorySize, FSM_TOT);

    // 1. split hidden + weights to bf16 hi/lo (W also transposed)
    conv_split<<<(TOTE / 4 + 255) / 256, 256>>>(hidden, xhi, xlo, TOTE / 4);
    dim3 wgrid(Dc / 32, Dc / 32), wblk(32, 8);
    conv_w_t<<<wgrid, wblk>>>(wq, whiT + 0 * DD, wloT + 0 * DD);
    conv_w_t<<<wgrid, wblk>>>(wk, whiT + 1 * DD, wloT + 1 * DD);
    conv_w_t<<<wgrid, wblk>>>(wv, whiT + 2 * DD, wloT + 2 * DD);
    conv_w_t<<<wgrid, wblk>>>(wo, whiT + 3 * DD, wloT + 3 * DD);

    // 2. QKV projections (HMMA)
    dim3 ggrid(Dc / 128, MTOT / 128);
    gemm_hmma<<<ggrid, 256, GSMEM_TOTAL>>>(xhi, xlo, whiT + 0 * DD, wloT + 0 * DD, q);
    gemm_hmma<<<ggrid, 256, GSMEM_TOTAL>>>(xhi, xlo, whiT + 1 * DD, wloT + 1 * DD, k);
    gemm_hmma<<<ggrid, 256, GSMEM_TOTAL>>>(xhi, xlo, whiT + 2 * DD, wloT + 2 * DD, v);

    // 3. rotary + splits for attention
    rotary_split<<<(Bc * Sc * Hc * 64) / 256, 256>>>(q, k, qhi, qlo, khi, klo);
    v_split<<<(TOTE / 2) / 256, 256>>>(v, vhi, vlo);

    // 4. attention (HMMA) — writes xhi/xlo for the output projection
    flash_mma<<<dim3(Sc / 128, Hc, Bc), 256, FSM_TOT>>>(qhi, qlo, khi, klo, vhi, vlo, xhi, xlo);

    // 5. output projection
    gemm_hmma<<<ggrid, 256, GSMEM_TOTAL>>>(xhi, xlo, whiT + 3 * DD, wloT + 3 * DD, out);
}

// round 12
// speedup vs baseline: 4.8738x; 1.1217x over previous
#include <cuda_runtime.h>
#include <cuda_fp16.h>
#include <cstdint>
#include <math.h>

// Problem dims
#define Bc  2
#define Sc  2048
#define Dc  2048
#define Hc  16
#define HDc 128
#define MTOT (Bc * Sc)            // 4096
#define TOTE (Bc * Sc * Dc)       // 8388608
#define DD   (Dc * Dc)            // 4194304

// ---------------------------------------------------------------------------
// Scratch (__device__ globals: allocation-free rule)
// ---------------------------------------------------------------------------
__device__ float g_q[TOTE];
__device__ float g_k[TOTE];
__device__ float g_v[TOTE];
__device__ __half g_xhi[TOTE];      // GEMM activation splits (hidden, then O)
__device__ __half g_xlo[TOTE];
__device__ __half g_whiT[4 * DD];   // W^T splits for wq,wk,wv,wo  [n][k]
__device__ __half g_wloT[4 * DD];
// attention operands, [b][h][s][128] layout
__device__ __half g_qhi[TOTE], g_qlo[TOTE];
__device__ __half g_khi[TOTE], g_klo[TOTE];
__device__ __half g_vhi[TOTE], g_vlo[TOTE];

// ---------------------------------------------------------------------------
// PTX helpers (baseline ISA: mma.sync / ldmatrix / cp.async — sm_103-safe)
// ---------------------------------------------------------------------------
__device__ __forceinline__ uint32_t smem_u32(const void* p) {
    uint32_t a;
    asm("{ .reg .u64 t; cvta.to.shared.u64 t, %1; cvt.u32.u64 %0, t; }" : "=r"(a) : "l"(p));
    return a;
}
__device__ __forceinline__ void ldsm4(uint32_t* r, uint32_t addr) {
    asm volatile("ldmatrix.sync.aligned.m8n8.x4.shared.b16 {%0,%1,%2,%3}, [%4];"
                 : "=r"(r[0]), "=r"(r[1]), "=r"(r[2]), "=r"(r[3]) : "r"(addr));
}
__device__ __forceinline__ void ldsm2(uint32_t* r, uint32_t addr) {
    asm volatile("ldmatrix.sync.aligned.m8n8.x2.shared.b16 {%0,%1}, [%2];"
                 : "=r"(r[0]), "=r"(r[1]) : "r"(addr));
}
__device__ __forceinline__ void ldsm2t(uint32_t* r, uint32_t addr) {
    asm volatile("ldmatrix.sync.aligned.m8n8.x2.trans.shared.b16 {%0,%1}, [%2];"
                 : "=r"(r[0]), "=r"(r[1]) : "r"(addr));
}
__device__ __forceinline__ void mma16816(float* c, const uint32_t* a, const uint32_t* b) {
    asm volatile("mma.sync.aligned.m16n8k16.row.col.f32.f16.f16.f32 "
                 "{%0,%1,%2,%3}, {%4,%5,%6,%7}, {%8,%9}, {%0,%1,%2,%3};"
                 : "+f"(c[0]), "+f"(c[1]), "+f"(c[2]), "+f"(c[3])
                 : "r"(a[0]), "r"(a[1]), "r"(a[2]), "r"(a[3]), "r"(b[0]), "r"(b[1]));
}
__device__ __forceinline__ void cp16(uint32_t smem, const void* g) {
    asm volatile("cp.async.cg.shared.global [%0], [%1], 16;" :: "r"(smem), "l"(g));
}
#define CP_COMMIT() asm volatile("cp.async.commit_group;" ::: "memory")
#define CP_WAIT(N)  asm volatile("cp.async.wait_group %0;" :: "n"(N) : "memory")

__device__ __forceinline__ void splitpack(float x, float y, uint32_t& hi, uint32_t& lo) {
    __half hx = __float2half(x), hy = __float2half(y);
    float lx = x - __half2float(hx), ly = y - __half2float(hy);
    __half2 hv(hx, hy);
    __half2 lv(__float2half(lx), __float2half(ly));
    hi = *(uint32_t*)&hv;
    lo = *(uint32_t*)&lv;
}
__device__ __forceinline__ uint32_t pack2h(float x, float y) {
    __half2 h(__float2half(x), __float2half(y));
    return *(uint32_t*)&h;
}
// 50*tanh(s/50) via __expf; graceful at large |s| (exp->inf => 1-0)
__device__ __forceinline__ float cap50(float s) {
    float e = __expf(s * 0.04f);
    return 50.f * (1.f - 2.f / (e + 1.f));
}

// ---------------------------------------------------------------------------
// fp32 -> fp16 hi/lo split (elementwise, float4 vectorized)
// ---------------------------------------------------------------------------
__global__ void conv_split(const float* __restrict__ in,
                           __half* __restrict__ hi, __half* __restrict__ lo, int n4)
{
    int i = blockIdx.x * blockDim.x + threadIdx.x;
    if (i >= n4) return;
    float4 v = ((const float4*)in)[i];
    uint32_t h0, l0, h1, l1;
    splitpack(v.x, v.y, h0, l0);
    splitpack(v.z, v.w, h1, l1);
    uint32_t* hp = (uint32_t*)hi;
    uint32_t* lp = (uint32_t*)lo;
    hp[2 * i] = h0; hp[2 * i + 1] = h1;
    lp[2 * i] = l0; lp[2 * i + 1] = l1;
}

// ---------------------------------------------------------------------------
// All 4 weights: W[k][n] fp32 -> W^T[n][k] fp16 hi/lo (z = weight index)
// ---------------------------------------------------------------------------
__global__ void conv_w_all(const float* __restrict__ w0, const float* __restrict__ w1,
                           const float* __restrict__ w2, const float* __restrict__ w3,
                           __half* __restrict__ hiT, __half* __restrict__ loT)
{
    __shared__ float tile[32][33];
    const float* w = (blockIdx.z == 0) ? w0 : (blockIdx.z == 1) ? w1
                   : (blockIdx.z == 2) ? w2 : w3;
    __half* hO = hiT + (size_t)blockIdx.z * DD;
    __half* lO = loT + (size_t)blockIdx.z * DD;
    int n0 = blockIdx.x * 32, k0 = blockIdx.y * 32;
    int tx = threadIdx.x, ty = threadIdx.y;   // 32 x 8
#pragma unroll
    for (int i = 0; i < 4; ++i)
        tile[ty + i * 8][tx] = w[(size_t)(k0 + ty + i * 8) * Dc + n0 + tx];
    __syncthreads();
#pragma unroll
    for (int i = 0; i < 4; ++i) {
        float v = tile[tx][ty + i * 8];
        __half h = __float2half(v);
        __half l = __float2half(v - __half2float(h));
        size_t oidx = (size_t)(n0 + ty + i * 8) * Dc + k0 + tx;
        hO[oidx] = h;
        lO[oidx] = l;
    }
}

// ---------------------------------------------------------------------------
// HMMA fp16 split GEMM: C[4096x2048] = A @ W
// NP=3: Ah*Bh + Ah*Bl + Al*Bh (near-exact). NP=2: Ah*Bh + Ah*Bl (A-rounding err).
// ---------------------------------------------------------------------------
#define GKT 32
#define ROWB 80
#define TILE_B (128 * ROWB)
#define STAGE_B (4 * TILE_B)
#define GSMEM_TOTAL (2 * STAGE_B)        // 81920

template<int NP>
__global__ __launch_bounds__(256) void gemm_hmma(
    const __half* __restrict__ Ahi, const __half* __restrict__ Alo,
    const __half* __restrict__ BhiT, const __half* __restrict__ BloT,
    float* __restrict__ C)
{
    extern __shared__ __align__(128) char smem[];
    const uint32_t sb = smem_u32(smem);
    const int t   = threadIdx.x;
    const int l   = t & 31;
    const int wid = t >> 5;
    const int wm  = wid >> 2;
    const int wn  = wid & 3;
    const int m0  = blockIdx.y * 128;
    const int n0  = blockIdx.x * 128;

    const int arow = (l & 7) + ((l >> 3) & 1) * 8;
    const int ak8  = (l >> 4);
    const uint32_t aoff = (uint32_t)((wm * 64 + arow) * ROWB + ak8 * 16);
    const int brow = l & 7;
    const int bk8  = (l >> 3) & 1;
    const uint32_t boff = (uint32_t)((wn * 32 + brow) * ROWB + bk8 * 16);

    const int r0c = (t * 2) >> 2, c0c = (t * 2) & 3;
    const int r1c = (t * 2 + 1) >> 2, c1c = (t * 2 + 1) & 3;

    float acc[4][4][4];
#pragma unroll
    for (int i = 0; i < 4; ++i)
#pragma unroll
        for (int j = 0; j < 4; ++j)
#pragma unroll
            for (int u = 0; u < 4; ++u) acc[i][j][u] = 0.f;

    const __half* srcs[4] = {Ahi, Alo, BhiT, BloT};

    auto load_tiles = [&](int kt, int s) {
        const uint32_t st = sb + s * STAGE_B;
#pragma unroll
        for (int tl = 0; tl < 4; ++tl) {
            if (NP == 2 && tl == 1) continue;       // no A-lo tile
            const __half* src = srcs[tl];
            const int rbase = (tl < 2) ? m0 : n0;
            cp16(st + tl * TILE_B + r0c * ROWB + c0c * 16,
                 src + (size_t)(rbase + r0c) * Dc + kt * GKT + c0c * 8);
            cp16(st + tl * TILE_B + r1c * ROWB + c1c * 16,
                 src + (size_t)(rbase + r1c) * Dc + kt * GKT + c1c * 8);
        }
    };

    load_tiles(0, 0);
    CP_COMMIT();

    for (int kt = 0; kt < Dc / GKT; ++kt) {
        if (kt + 1 < Dc / GKT) {
            load_tiles(kt + 1, (kt + 1) & 1);
            CP_COMMIT();
            CP_WAIT(1);
        } else {
            CP_WAIT(0);
        }
        __syncthreads();

        const uint32_t st = sb + (kt & 1) * STAGE_B;
        const uint32_t aHi = st + 0 * TILE_B + aoff;
        const uint32_t aLo = st + 1 * TILE_B + aoff;
        const uint32_t bHi = st + 2 * TILE_B + boff;
        const uint32_t bLo = st + 3 * TILE_B + boff;

#pragma unroll
        for (int ks = 0; ks < 2; ++ks) {
            uint32_t ah[4][4], al[4][4], bh[4][2], bl[4][2];
#pragma unroll
            for (int mt = 0; mt < 4; ++mt) {
                ldsm4(ah[mt], aHi + mt * (16 * ROWB) + ks * 32);
                if (NP == 3) ldsm4(al[mt], aLo + mt * (16 * ROWB) + ks * 32);
            }
#pragma unroll
            for (int nt = 0; nt < 4; ++nt) {
                ldsm2(bh[nt], bHi + nt * (8 * ROWB) + ks * 32);
                ldsm2(bl[nt], bLo + nt * (8 * ROWB) + ks * 32);
            }
#pragma unroll
            for (int mt = 0; mt < 4; ++mt)
#pragma unroll
                for (int nt = 0; nt < 4; ++nt)
                    mma16816(acc[mt][nt], ah[mt], bh[nt]);
#pragma unroll
            for (int mt = 0; mt < 4; ++mt)
#pragma unroll
                for (int nt = 0; nt < 4; ++nt)
                    mma16816(acc[mt][nt], ah[mt], bl[nt]);
            if (NP == 3) {
#pragma unroll
                for (int mt = 0; mt < 4; ++mt)
#pragma unroll
                    for (int nt = 0; nt < 4; ++nt)
                        mma16816(acc[mt][nt], al[mt], bh[nt]);
            }
        }
        __syncthreads();
    }

    const int erow = m0 + wm * 64 + (l >> 2);
    const int ecol = n0 + wn * 32 + (l & 3) * 2;
#pragma unroll
    for (int mt = 0; mt < 4; ++mt)
#pragma unroll
        for (int nt = 0; nt < 4; ++nt) {
            *(float2*)&C[(size_t)(erow + mt * 16) * Dc + ecol + nt * 8] =
                make_float2(acc[mt][nt][0], acc[mt][nt][1]);
            *(float2*)&C[(size_t)(erow + mt * 16 + 8) * Dc + ecol + nt * 8] =
                make_float2(acc[mt][nt][2], acc[mt][nt][3]);
        }
}

// ---------------------------------------------------------------------------
// Rotary + fp16 hi/lo split: fp32 [b][s][h*128+d] -> fp16 [b][h][s][128]
// ---------------------------------------------------------------------------
__global__ void rotary_split(const float* __restrict__ q, const float* __restrict__ k,
                             __half* __restrict__ qhi, __half* __restrict__ qlo,
                             __half* __restrict__ khi, __half* __restrict__ klo)
{
    int idx = blockIdx.x * blockDim.x + threadIdx.x;
    if (idx >= Bc * Sc * Hc * 64) return;
    int j = idx & 63;
    int h = (idx >> 6) & (Hc - 1);
    int s = (idx >> 10) & (Sc - 1);
    int b = idx >> 21;

    float inv_freq = 1.0f / powf(10000.0f, (float)j * (1.0f / 64.0f));
    float sn, cs;
    sincosf((float)s * inv_freq, &sn, &cs);

    size_t ib = ((size_t)(b * Sc + s)) * Dc + h * HDc + j;
    size_t ob = ((size_t)((b * Hc + h) * Sc + s)) * HDc + j;

    float q1 = q[ib], q2 = q[ib + 64];
    float qa = q1 * cs - q2 * sn;
    float qb = q2 * cs + q1 * sn;
    float k1 = k[ib], k2 = k[ib + 64];
    float ka = k1 * cs - k2 * sn;
    float kb = k2 * cs + k1 * sn;

    __half hqa = __float2half(qa), hqb = __float2half(qb);
    __half hka = __float2half(ka), hkb = __float2half(kb);
    qhi[ob] = hqa;      qhi[ob + 64] = hqb;
    qlo[ob] = __float2half(qa - __half2float(hqa));
    qlo[ob + 64] = __float2half(qb - __half2float(hqb));
    khi[ob] = hka;      khi[ob + 64] = hkb;
    klo[ob] = __float2half(ka - __half2float(hka));
    klo[ob + 64] = __float2half(kb - __half2float(hkb));
}

// ---------------------------------------------------------------------------
// V split: fp32 [b][s][h*128+d] -> fp16 hi/lo [b][h][s][128]
// ---------------------------------------------------------------------------
__global__ void v_split(const float* __restrict__ v,
                        __half* __restrict__ vhi, __half* __restrict__ vlo)
{
    int idx = blockIdx.x * blockDim.x + threadIdx.x;
    if (idx >= TOTE / 2) return;
    int d2 = idx & 63;
    int h = (idx >> 6) & (Hc - 1);
    int s = (idx >> 10) & (Sc - 1);
    int b = idx >> 21;
    const float2 vv = *(const float2*)&v[((size_t)(b * Sc + s)) * Dc + h * HDc + d2 * 2];
    uint32_t hp, lp;
    splitpack(vv.x, vv.y, hp, lp);
    size_t ob = ((size_t)((b * Hc + h) * Sc + s)) * HDc + d2 * 2;
    *(uint32_t*)&vhi[ob] = hp;
    *(uint32_t*)&vlo[ob] = lp;
}

// ---------------------------------------------------------------------------
// Flash attention on HMMA: QK 3-product, PV 2-product (P single fp16),
// causal + tanh cap + Lingvo softmax (phantom 0-logit: m=0, l=1).
// CTA: 128 q rows x KV tiles of 64; 8 warps; 2-stage cp.async K/V.
// Writes O directly as fp16 (hi only) for the 2-product WO projection.
// ---------------------------------------------------------------------------
#define FSM_Q   0
#define FSM_ST  65536
#define FSM_TOT (65536 + 2 * 65536)      // 196608 = 192KB

__global__ __launch_bounds__(256) void flash_mma(
    const __half* __restrict__ qhi, const __half* __restrict__ qlo,
    const __half* __restrict__ khi, const __half* __restrict__ klo,
    const __half* __restrict__ vhi, const __half* __restrict__ vlo,
    __half* __restrict__ Ohi)
{
    extern __shared__ __align__(128) char smem[];
    const uint32_t sb = smem_u32(smem);
    const int t = threadIdx.x, l = t & 31, w = t >> 5;
    const int qi = (Sc / 128 - 1) - blockIdx.x;        // heavy CTAs first
    const int h = blockIdx.y, b = blockIdx.z;
    const size_t hb = (size_t)(b * Hc + h) * Sc * HDc;

#pragma unroll
    for (int i = 0; i < 8; ++i) {
        int c = t + 256 * i;
        int row = c >> 4, c16 = c & 15;
        uint32_t dst = (uint32_t)(row * 256 + ((c16 ^ (row & 7)) * 16));
        size_t src = hb + (size_t)(qi * 128 + row) * HDc + c16 * 8;
        cp16(sb + FSM_Q + dst, qhi + src);
        cp16(sb + FSM_Q + 32768 + dst, qlo + src);
    }
    auto load_kv = [&](int j, int st) {
        uint32_t stb = sb + FSM_ST + st * 65536;
#pragma unroll
        for (int i = 0; i < 4; ++i) {
            int c = t + 256 * i;
            int row = c >> 4, c16 = c & 15;
            uint32_t dst = (uint32_t)(row * 256 + ((c16 ^ (row & 7)) * 16));
            size_t src = hb + (size_t)(j * 64 + row) * HDc + c16 * 8;
            cp16(stb + dst,         khi + src);
            cp16(stb + 16384 + dst, klo + src);
            cp16(stb + 32768 + dst, vhi + src);
            cp16(stb + 49152 + dst, vlo + src);
        }
    };
    load_kv(0, 0);
    CP_COMMIT();

    float accO[16][4];
#pragma unroll
    for (int n = 0; n < 16; ++n)
#pragma unroll
        for (int e = 0; e < 4; ++e) accO[n][e] = 0.f;
    float m0 = 0.f, m1 = 0.f, l0 = 1.f, l1 = 1.f;

    const int aRow = 16 * w + (l & 15);
    const int aK8  = l >> 4;
    const int bRowL = l & 7;
    const int bK8   = (l >> 3) & 1;
    const int vRow0 = (l & 7) + 8 * ((l >> 3) & 1);

    const int nt = 2 * qi + 2;
    for (int j = 0; j < nt; ++j) {
        if (j + 1 < nt) {
            load_kv(j + 1, (j + 1) & 1);
            CP_COMMIT();
            CP_WAIT(1);
        } else {
            CP_WAIT(0);
        }
        __syncthreads();

        const uint32_t stb = sb + FSM_ST + (j & 1) * 65536;
        const uint32_t sKh = stb, sKl = stb + 16384;
        const uint32_t sVh = stb + 32768, sVl = stb + 49152;

        // ---- S = Q K^T (3-product) ----
        float accS[8][4];
#pragma unroll
        for (int n = 0; n < 8; ++n)
#pragma unroll
            for (int e = 0; e < 4; ++e) accS[n][e] = 0.f;

#pragma unroll
        for (int k = 0; k < 8; ++k) {
            uint32_t ah[4], al[4];
            int ac16 = 2 * k + aK8;
            uint32_t aoff = (uint32_t)(aRow * 256 + ((ac16 ^ (aRow & 7)) * 16));
            ldsm4(ah, sb + FSM_Q + aoff);
            ldsm4(al, sb + FSM_Q + 32768 + aoff);
#pragma unroll
            for (int n = 0; n < 8; ++n) {
                int brow = 8 * n + bRowL;
                int bc16 = 2 * k + bK8;
                uint32_t boff = (uint32_t)(brow * 256 + ((bc16 ^ (brow & 7)) * 16));
                uint32_t bh2[2], bl2[2];
                ldsm2(bh2, sKh + boff);
                ldsm2(bl2, sKl + boff);
                mma16816(accS[n], ah, bh2);
                mma16816(accS[n], ah, bl2);
                mma16816(accS[n], al, bh2);
            }
        }

        // ---- tanh cap + causal mask (fast math) ----
#pragma unroll
        for (int n = 0; n < 8; ++n)
#pragma unroll
            for (int e = 0; e < 4; ++e)
                accS[n][e] = cap50(accS[n][e]);

        if (j >= 2 * qi) {
            int r0 = 16 * w + (l >> 2);
            int cb = j * 64 - qi * 128 + 2 * (l & 3);
#pragma unroll
            for (int n = 0; n < 8; ++n) {
                int c = cb + 8 * n;
                if (c     > r0)     accS[n][0] = -50.f;
                if (c + 1 > r0)     accS[n][1] = -50.f;
                if (c     > r0 + 8) accS[n][2] = -50.f;
                if (c + 1 > r0 + 8) accS[n][3] = -50.f;
            }
        }

        // ---- online softmax ----
        float mx0 = -1e30f, mx1 = -1e30f;
#pragma unroll
        for (int n = 0; n < 8; ++n) {
            mx0 = fmaxf(mx0, fmaxf(accS[n][0], accS[n][1]));
            mx1 = fmaxf(mx1, fmaxf(accS[n][2], accS[n][3]));
        }
        mx0 = fmaxf(mx0, __shfl_xor_sync(0xffffffffu, mx0, 1));
        mx0 = fmaxf(mx0, __shfl_xor_sync(0xffffffffu, mx0, 2));
        mx1 = fmaxf(mx1, __shfl_xor_sync(0xffffffffu, mx1, 1));
        mx1 = fmaxf(mx1, __shfl_xor_sync(0xffffffffu, mx1, 2));
        float mn0 = fmaxf(m0, mx0), mn1 = fmaxf(m1, mx1);
        float sc0 = __expf(m0 - mn0), sc1 = __expf(m1 - mn1);
        float rs0 = 0.f, rs1 = 0.f;
#pragma unroll
        for (int n = 0; n < 8; ++n) {
            accS[n][0] = __expf(accS[n][0] - mn0); rs0 += accS[n][0];
            accS[n][1] = __expf(accS[n][1] - mn0); rs0 += accS[n][1];
            accS[n][2] = __expf(accS[n][2] - mn1); rs1 += accS[n][2];
            accS[n][3] = __expf(accS[n][3] - mn1); rs1 += accS[n][3];
        }
        rs0 += __shfl_xor_sync(0xffffffffu, rs0, 1);
        rs0 += __shfl_xor_sync(0xffffffffu, rs0, 2);
        rs1 += __shfl_xor_sync(0xffffffffu, rs1, 1);
        rs1 += __shfl_xor_sync(0xffffffffu, rs1, 2);
        l0 = l0 * sc0 + rs0;  m0 = mn0;
        l1 = l1 * sc1 + rs1;  m1 = mn1;
#pragma unroll
        for (int n = 0; n < 16; ++n) {
            accO[n][0] *= sc0; accO[n][1] *= sc0;
            accO[n][2] *= sc1; accO[n][3] *= sc1;
        }

        // ---- O += P V (2-product: P fp16 single, V 2-split) ----
#pragma unroll
        for (int kk = 0; kk < 4; ++kk) {
            uint32_t pa[4];
            pa[0] = pack2h(accS[2 * kk][0],     accS[2 * kk][1]);
            pa[1] = pack2h(accS[2 * kk][2],     accS[2 * kk][3]);
            pa[2] = pack2h(accS[2 * kk + 1][0], accS[2 * kk + 1][1]);
            pa[3] = pack2h(accS[2 * kk + 1][2], accS[2 * kk + 1][3]);
#pragma unroll
            for (int n = 0; n < 16; ++n) {
                int vrow = 16 * kk + vRow0;
                int vc16 = n ^ (vrow & 7);
                uint32_t voff = (uint32_t)(vrow * 256 + vc16 * 16);
                uint32_t vh2[2], vl2[2];
                ldsm2t(vh2, sVh + voff);
                ldsm2t(vl2, sVl + voff);
                mma16816(accO[n], pa, vh2);
                mma16816(accO[n], pa, vl2);
            }
        }
        __syncthreads();
    }

    // ---- write O as fp16 (hi only) in [b][s][h*128+d] layout ----
    float i0 = 1.f / l0, i1 = 1.f / l1;
    int row0 = qi * 128 + 16 * w + (l >> 2);
    size_t ob0 = ((size_t)b * Sc + row0) * Dc + h * HDc;
    size_t ob1 = ob0 + 8 * (size_t)Dc;
#pragma unroll
    for (int n = 0; n < 16; ++n) {
        int d = 8 * n + 2 * (l & 3);
        *(uint32_t*)&Ohi[ob0 + d] = pack2h(accO[n][0] * i0, accO[n][1] * i0);
        *(uint32_t*)&Ohi[ob1 + d] = pack2h(accO[n][2] * i1, accO[n][3] * i1);
    }
}

// ---------------------------------------------------------------------------
extern "C" void kernel_launch(void* const* d_in, const int* in_sizes, int n_in,
                              void* d_out, int out_size)
{
    const float* hidden = (const float*)d_in[0];
    const float* wq = (const float*)d_in[1];
    const float* wk = (const float*)d_in[2];
    const float* wv = (const float*)d_in[3];
    const float* wo = (const float*)d_in[4];
    float* out = (float*)d_out;

    float *q, *k, *v;
    __half *xhi, *xlo, *whiT, *wloT;
    __half *qhi, *qlo, *khi, *klo, *vhi, *vlo;
    cudaGetSymbolAddress((void**)&q, g_q);
    cudaGetSymbolAddress((void**)&k, g_k);
    cudaGetSymbolAddress((void**)&v, g_v);
    cudaGetSymbolAddress((void**)&xhi, g_xhi);
    cudaGetSymbolAddress((void**)&xlo, g_xlo);
    cudaGetSymbolAddress((void**)&whiT, g_whiT);
    cudaGetSymbolAddress((void**)&wloT, g_wloT);
    cudaGetSymbolAddress((void**)&qhi, g_qhi);
    cudaGetSymbolAddress((void**)&qlo, g_qlo);
    cudaGetSymbolAddress((void**)&khi, g_khi);
    cudaGetSymbolAddress((void**)&klo, g_klo);
    cudaGetSymbolAddress((void**)&vhi, g_vhi);
    cudaGetSymbolAddress((void**)&vlo, g_vlo);

    cudaFuncSetAttribute(gemm_hmma<3>, cudaFuncAttributeMaxDynamicSharedMemorySize, GSMEM_TOTAL);
    cudaFuncSetAttribute(gemm_hmma<2>, cudaFuncAttributeMaxDynamicSharedMemorySize, GSMEM_TOTAL);
    cudaFuncSetAttribute(flash_mma, cudaFuncAttributeMaxDynamicSharedMemorySize, FSM_TOT);

    // 1. splits
    conv_split<<<(TOTE / 4 + 255) / 256, 256>>>(hidden, xhi, xlo, TOTE / 4);
    conv_w_all<<<dim3(Dc / 32, Dc / 32, 4), dim3(32, 8)>>>(wq, wk, wv, wo, whiT, wloT);

    // 2. QKV projections (Q,K 3-product; V 2-product)
    dim3 ggrid(Dc / 128, MTOT / 128);
    gemm_hmma<3><<<ggrid, 256, GSMEM_TOTAL>>>(xhi, xlo, whiT + 0 * DD, wloT + 0 * DD, q);
    gemm_hmma<3><<<ggrid, 256, GSMEM_TOTAL>>>(xhi, xlo, whiT + 1 * DD, wloT + 1 * DD, k);
    gemm_hmma<2><<<ggrid, 256, GSMEM_TOTAL>>>(xhi, xlo, whiT + 2 * DD, wloT + 2 * DD, v);

    // 3. rotary + splits for attention
    rotary_split<<<(Bc * Sc * Hc * 64) / 256, 256>>>(q, k, qhi, qlo, khi, klo);
    v_split<<<(TOTE / 2) / 256, 256>>>(v, vhi, vlo);

    // 4. attention — writes xhi (fp16 O) for the output projection
    flash_mma<<<dim3(Sc / 128, Hc, Bc), 256, FSM_TOT>>>(qhi, qlo, khi, klo, vhi, vlo, xhi);

    // 5. output projection (2-product)
    gemm_hmma<2><<<ggrid, 256, GSMEM_TOTAL>>>(xhi, xlo, whiT + 3 * DD, wloT + 3 * DD, out);
}

// round 13
// speedup vs baseline: 5.3207x; 1.0917x over previous
#include <cuda_runtime.h>
#include <cuda_fp16.h>
#include <cstdint>
#include <math.h>

// Problem dims
#define Bc  2
#define Sc  2048
#define Dc  2048
#define Hc  16
#define HDc 128
#define MTOT (Bc * Sc)            // 4096
#define TOTE (Bc * Sc * Dc)       // 8388608
#define DD   (Dc * Dc)            // 4194304

// ---------------------------------------------------------------------------
// Scratch (__device__ globals: allocation-free rule)
// ---------------------------------------------------------------------------
__device__ float g_q[TOTE];
__device__ float g_k[TOTE];
__device__ float g_v[TOTE];
__device__ __half g_xhi[TOTE];      // GEMM activation splits (hidden, then O)
__device__ __half g_xlo[TOTE];
__device__ __half g_whiT[4 * DD];   // W^T splits for wq,wk,wv,wo  [n][k]
__device__ __half g_wloT[4 * DD];
// attention operands, [b][h][s][128] layout
__device__ __half g_qhi[TOTE], g_qlo[TOTE];
__device__ __half g_khi[TOTE], g_klo[TOTE];
__device__ __half g_vhi[TOTE], g_vlo[TOTE];

// ---------------------------------------------------------------------------
// PTX helpers (baseline ISA: mma.sync / ldmatrix / cp.async — sm_103-safe)
// ---------------------------------------------------------------------------
__device__ __forceinline__ uint32_t smem_u32(const void* p) {
    uint32_t a;
    asm("{ .reg .u64 t; cvta.to.shared.u64 t, %1; cvt.u32.u64 %0, t; }" : "=r"(a) : "l"(p));
    return a;
}
__device__ __forceinline__ void ldsm4(uint32_t* r, uint32_t addr) {
    asm volatile("ldmatrix.sync.aligned.m8n8.x4.shared.b16 {%0,%1,%2,%3}, [%4];"
                 : "=r"(r[0]), "=r"(r[1]), "=r"(r[2]), "=r"(r[3]) : "r"(addr));
}
__device__ __forceinline__ void ldsm2(uint32_t* r, uint32_t addr) {
    asm volatile("ldmatrix.sync.aligned.m8n8.x2.shared.b16 {%0,%1}, [%2];"
                 : "=r"(r[0]), "=r"(r[1]) : "r"(addr));
}
__device__ __forceinline__ void ldsm2t(uint32_t* r, uint32_t addr) {
    asm volatile("ldmatrix.sync.aligned.m8n8.x2.trans.shared.b16 {%0,%1}, [%2];"
                 : "=r"(r[0]), "=r"(r[1]) : "r"(addr));
}
__device__ __forceinline__ void mma16816(float* c, const uint32_t* a, const uint32_t* b) {
    asm volatile("mma.sync.aligned.m16n8k16.row.col.f32.f16.f16.f32 "
                 "{%0,%1,%2,%3}, {%4,%5,%6,%7}, {%8,%9}, {%0,%1,%2,%3};"
                 : "+f"(c[0]), "+f"(c[1]), "+f"(c[2]), "+f"(c[3])
                 : "r"(a[0]), "r"(a[1]), "r"(a[2]), "r"(a[3]), "r"(b[0]), "r"(b[1]));
}
__device__ __forceinline__ void cp16(uint32_t smem, const void* g) {
    asm volatile("cp.async.cg.shared.global [%0], [%1], 16;" :: "r"(smem), "l"(g));
}
#define CP_COMMIT() asm volatile("cp.async.commit_group;" ::: "memory")
#define CP_WAIT(N)  asm volatile("cp.async.wait_group %0;" :: "n"(N) : "memory")

__device__ __forceinline__ void splitpack(float x, float y, uint32_t& hi, uint32_t& lo) {
    __half hx = __float2half(x), hy = __float2half(y);
    float lx = x - __half2float(hx), ly = y - __half2float(hy);
    __half2 hv(hx, hy);
    __half2 lv(__float2half(lx), __float2half(ly));
    hi = *(uint32_t*)&hv;
    lo = *(uint32_t*)&lv;
}
__device__ __forceinline__ uint32_t pack2h(float x, float y) {
    __half2 h(__float2half(x), __float2half(y));
    return *(uint32_t*)&h;
}
// 50*tanh(s/50) via __expf; graceful at large |s|
__device__ __forceinline__ float cap50(float s) {
    float e = __expf(s * 0.04f);
    return 50.f * (1.f - 2.f / (e + 1.f));
}

// ---------------------------------------------------------------------------
// fp32 -> fp16 hi/lo split (elementwise, float4 vectorized)
// ---------------------------------------------------------------------------
__global__ void conv_split(const float* __restrict__ in,
                           __half* __restrict__ hi, __half* __restrict__ lo, int n4)
{
    int i = blockIdx.x * blockDim.x + threadIdx.x;
    if (i >= n4) return;
    float4 v = ((const float4*)in)[i];
    uint32_t h0, l0, h1, l1;
    splitpack(v.x, v.y, h0, l0);
    splitpack(v.z, v.w, h1, l1);
    uint32_t* hp = (uint32_t*)hi;
    uint32_t* lp = (uint32_t*)lo;
    hp[2 * i] = h0; hp[2 * i + 1] = h1;
    lp[2 * i] = l0; lp[2 * i + 1] = l1;
}

// ---------------------------------------------------------------------------
// All 4 weights: W[k][n] fp32 -> W^T[n][k] fp16 hi/lo (z = weight index)
// ---------------------------------------------------------------------------
__global__ void conv_w_all(const float* __restrict__ w0, const float* __restrict__ w1,
                           const float* __restrict__ w2, const float* __restrict__ w3,
                           __half* __restrict__ hiT, __half* __restrict__ loT)
{
    __shared__ float tile[32][33];
    const float* w = (blockIdx.z == 0) ? w0 : (blockIdx.z == 1) ? w1
                   : (blockIdx.z == 2) ? w2 : w3;
    __half* hO = hiT + (size_t)blockIdx.z * DD;
    __half* lO = loT + (size_t)blockIdx.z * DD;
    int n0 = blockIdx.x * 32, k0 = blockIdx.y * 32;
    int tx = threadIdx.x, ty = threadIdx.y;   // 32 x 8
#pragma unroll
    for (int i = 0; i < 4; ++i)
        tile[ty + i * 8][tx] = w[(size_t)(k0 + ty + i * 8) * Dc + n0 + tx];
    __syncthreads();
#pragma unroll
    for (int i = 0; i < 4; ++i) {
        float v = tile[tx][ty + i * 8];
        __half h = __float2half(v);
        __half l = __float2half(v - __half2float(h));
        size_t oidx = (size_t)(n0 + ty + i * 8) * Dc + k0 + tx;
        hO[oidx] = h;
        lO[oidx] = l;
    }
}

// ---------------------------------------------------------------------------
// HMMA fp16 split GEMM: C[4096x2048] = A @ W
// CTA tile 128x64, 8 warps (4x2), warp tile 32x32 — sized for 3 CTAs/SM.
// NP=3: Ah*Bh + Ah*Bl + Al*Bh. NP=2: Ah*Bh + Ah*Bl.
// ---------------------------------------------------------------------------
#define GKT 32
#define ROWB 80                          // 32 halfs + 8 pad
#define TILE_A_B (128 * ROWB)            // 10240
#define TILE_B_B (64 * ROWB)             // 5120
#define OFF_AHI 0
#define OFF_ALO TILE_A_B
#define OFF_BHI (2 * TILE_A_B)
#define OFF_BLO (2 * TILE_A_B + TILE_B_B)
#define STAGE_B (2 * TILE_A_B + 2 * TILE_B_B)  // 30720
#define GSMEM_TOTAL (2 * STAGE_B)              // 61440

template<int NP>
__global__ __launch_bounds__(256, 3) void gemm_hmma(
    const __half* __restrict__ Ahi, const __half* __restrict__ Alo,
    const __half* __restrict__ BhiT, const __half* __restrict__ BloT,
    float* __restrict__ C)
{
    extern __shared__ __align__(128) char smem[];
    const uint32_t sb = smem_u32(smem);
    const int t   = threadIdx.x;
    const int l   = t & 31;
    const int wid = t >> 5;
    const int wm  = wid >> 1;            // 0..3 -> m offset wm*32
    const int wn  = wid & 1;             // 0..1 -> n offset wn*32
    const int m0  = blockIdx.y * 128;
    const int n0  = blockIdx.x * 64;

    // ldmatrix lane address components
    const int arow = (l & 7) + ((l >> 3) & 1) * 8;
    const int ak8  = (l >> 4);
    const uint32_t aoff = (uint32_t)((wm * 32 + arow) * ROWB + ak8 * 16);
    const int brow = l & 7;
    const int bk8  = (l >> 3) & 1;
    const uint32_t boff = (uint32_t)((wn * 32 + brow) * ROWB + bk8 * 16);

    float acc[2][4][4];
#pragma unroll
    for (int i = 0; i < 2; ++i)
#pragma unroll
        for (int j = 0; j < 4; ++j)
#pragma unroll
            for (int u = 0; u < 4; ++u) acc[i][j][u] = 0.f;

    // chunk map: 1536 16B chunks/stage (NP3): [0,512) Ahi, [512,1024) Alo,
    // [1024,1280) Bhi, [1280,1536) Blo. i=2,3 cover Alo exactly -> skipped NP2.
    auto load_tiles = [&](int kt, int s) {
        const uint32_t st = sb + s * STAGE_B;
#pragma unroll
        for (int i = 0; i < 6; ++i) {
            if (NP == 2 && (i == 2 || i == 3)) continue;
            int c = t + 256 * i;
            const __half* src;
            uint32_t toff;
            int rbase, local;
            if (c < 512)        { src = Ahi;  toff = OFF_AHI; rbase = m0; local = c; }
            else if (c < 1024)  { src = Alo;  toff = OFF_ALO; rbase = m0; local = c - 512; }
            else if (c < 1280)  { src = BhiT; toff = OFF_BHI; rbase = n0; local = c - 1024; }
            else                { src = BloT; toff = OFF_BLO; rbase = n0; local = c - 1280; }
            int row = local >> 2, ch = local & 3;
            cp16(st + toff + row * ROWB + ch * 16,
                 src + (size_t)(rbase + row) * Dc + kt * GKT + ch * 8);
        }
    };

    load_tiles(0, 0);
    CP_COMMIT();

    for (int kt = 0; kt < Dc / GKT; ++kt) {
        if (kt + 1 < Dc / GKT) {
            load_tiles(kt + 1, (kt + 1) & 1);
            CP_COMMIT();
            CP_WAIT(1);
        } else {
            CP_WAIT(0);
        }
        __syncthreads();

        const uint32_t st = sb + (kt & 1) * STAGE_B;

#pragma unroll
        for (int ks = 0; ks < 2; ++ks) {
            uint32_t ah[2][4], al[2][4], bh[4][2], bl[4][2];
#pragma unroll
            for (int mt = 0; mt < 2; ++mt) {
                ldsm4(ah[mt], st + OFF_AHI + aoff + mt * (16 * ROWB) + ks * 32);
                if (NP == 3)
                    ldsm4(al[mt], st + OFF_ALO + aoff + mt * (16 * ROWB) + ks * 32);
            }
#pragma unroll
            for (int nt = 0; nt < 4; ++nt) {
                ldsm2(bh[nt], st + OFF_BHI + boff + nt * (8 * ROWB) + ks * 32);
                ldsm2(bl[nt], st + OFF_BLO + boff + nt * (8 * ROWB) + ks * 32);
            }
#pragma unroll
            for (int mt = 0; mt < 2; ++mt)
#pragma unroll
                for (int nt = 0; nt < 4; ++nt)
                    mma16816(acc[mt][nt], ah[mt], bh[nt]);
#pragma unroll
            for (int mt = 0; mt < 2; ++mt)
#pragma unroll
                for (int nt = 0; nt < 4; ++nt)
                    mma16816(acc[mt][nt], ah[mt], bl[nt]);
            if (NP == 3) {
#pragma unroll
                for (int mt = 0; mt < 2; ++mt)
#pragma unroll
                    for (int nt = 0; nt < 4; ++nt)
                        mma16816(acc[mt][nt], al[mt], bh[nt]);
            }
        }
        __syncthreads();
    }

    const int erow = m0 + wm * 32 + (l >> 2);
    const int ecol = n0 + wn * 32 + (l & 3) * 2;
#pragma unroll
    for (int mt = 0; mt < 2; ++mt)
#pragma unroll
        for (int nt = 0; nt < 4; ++nt) {
            *(float2*)&C[(size_t)(erow + mt * 16) * Dc + ecol + nt * 8] =
                make_float2(acc[mt][nt][0], acc[mt][nt][1]);
            *(float2*)&C[(size_t)(erow + mt * 16 + 8) * Dc + ecol + nt * 8] =
                make_float2(acc[mt][nt][2], acc[mt][nt][3]);
        }
}

// ---------------------------------------------------------------------------
// Rotary + fp16 hi/lo split: fp32 [b][s][h*128+d] -> fp16 [b][h][s][128]
// ---------------------------------------------------------------------------
__global__ void rotary_split(const float* __restrict__ q, const float* __restrict__ k,
                             __half* __restrict__ qhi, __half* __restrict__ qlo,
                             __half* __restrict__ khi, __half* __restrict__ klo)
{
    int idx = blockIdx.x * blockDim.x + threadIdx.x;
    if (idx >= Bc * Sc * Hc * 64) return;
    int j = idx & 63;
    int h = (idx >> 6) & (Hc - 1);
    int s = (idx >> 10) & (Sc - 1);
    int b = idx >> 21;

    float inv_freq = 1.0f / powf(10000.0f, (float)j * (1.0f / 64.0f));
    float sn, cs;
    sincosf((float)s * inv_freq, &sn, &cs);

    size_t ib = ((size_t)(b * Sc + s)) * Dc + h * HDc + j;
    size_t ob = ((size_t)((b * Hc + h) * Sc + s)) * HDc + j;

    float q1 = q[ib], q2 = q[ib + 64];
    float qa = q1 * cs - q2 * sn;
    float qb = q2 * cs + q1 * sn;
    float k1 = k[ib], k2 = k[ib + 64];
    float ka = k1 * cs - k2 * sn;
    float kb = k2 * cs + k1 * sn;

    __half hqa = __float2half(qa), hqb = __float2half(qb);
    __half hka = __float2half(ka), hkb = __float2half(kb);
    qhi[ob] = hqa;      qhi[ob + 64] = hqb;
    qlo[ob] = __float2half(qa - __half2float(hqa));
    qlo[ob + 64] = __float2half(qb - __half2float(hqb));
    khi[ob] = hka;      khi[ob + 64] = hkb;
    klo[ob] = __float2half(ka - __half2float(hka));
    klo[ob + 64] = __float2half(kb - __half2float(hkb));
}

// ---------------------------------------------------------------------------
// V split: fp32 [b][s][h*128+d] -> fp16 hi/lo [b][h][s][128]
// ---------------------------------------------------------------------------
__global__ void v_split(const float* __restrict__ v,
                        __half* __restrict__ vhi, __half* __restrict__ vlo)
{
    int idx = blockIdx.x * blockDim.x + threadIdx.x;
    if (idx >= TOTE / 2) return;
    int d2 = idx & 63;
    int h = (idx >> 6) & (Hc - 1);
    int s = (idx >> 10) & (Sc - 1);
    int b = idx >> 21;
    const float2 vv = *(const float2*)&v[((size_t)(b * Sc + s)) * Dc + h * HDc + d2 * 2];
    uint32_t hp, lp;
    splitpack(vv.x, vv.y, hp, lp);
    size_t ob = ((size_t)((b * Hc + h) * Sc + s)) * HDc + d2 * 2;
    *(uint32_t*)&vhi[ob] = hp;
    *(uint32_t*)&vlo[ob] = lp;
}

// ---------------------------------------------------------------------------
// Flash attention on HMMA: QK 3-product, PV 2-product (P single fp16),
// causal + tanh cap + Lingvo softmax (phantom 0-logit: m=0, l=1).
// CTA: 128 q rows x KV tiles of 64; 8 warps; 2-stage cp.async K/V.
// ---------------------------------------------------------------------------
#define FSM_Q   0
#define FSM_ST  65536
#define FSM_TOT (65536 + 2 * 65536)      // 196608 = 192KB

__global__ __launch_bounds__(256) void flash_mma(
    const __half* __restrict__ qhi, const __half* __restrict__ qlo,
    const __half* __restrict__ khi, const __half* __restrict__ klo,
    const __half* __restrict__ vhi, const __half* __restrict__ vlo,
    __half* __restrict__ Ohi)
{
    extern __shared__ __align__(128) char smem[];
    const uint32_t sb = smem_u32(smem);
    const int t = threadIdx.x, l = t & 31, w = t >> 5;
    const int qi = (Sc / 128 - 1) - blockIdx.x;        // heavy CTAs first
    const int h = blockIdx.y, b = blockIdx.z;
    const size_t hb = (size_t)(b * Hc + h) * Sc * HDc;

#pragma unroll
    for (int i = 0; i < 8; ++i) {
        int c = t + 256 * i;
        int row = c >> 4, c16 = c & 15;
        uint32_t dst = (uint32_t)(row * 256 + ((c16 ^ (row & 7)) * 16));
        size_t src = hb + (size_t)(qi * 128 + row) * HDc + c16 * 8;
        cp16(sb + FSM_Q + dst, qhi + src);
        cp16(sb + FSM_Q + 32768 + dst, qlo + src);
    }
    auto load_kv = [&](int j, int st) {
        uint32_t stb = sb + FSM_ST + st * 65536;
#pragma unroll
        for (int i = 0; i < 4; ++i) {
            int c = t + 256 * i;
            int row = c >> 4, c16 = c & 15;
            uint32_t dst = (uint32_t)(row * 256 + ((c16 ^ (row & 7)) * 16));
            size_t src = hb + (size_t)(j * 64 + row) * HDc + c16 * 8;
            cp16(stb + dst,         khi + src);
            cp16(stb + 16384 + dst, klo + src);
            cp16(stb + 32768 + dst, vhi + src);
            cp16(stb + 49152 + dst, vlo + src);
        }
    };
    load_kv(0, 0);
    CP_COMMIT();

    float accO[16][4];
#pragma unroll
    for (int n = 0; n < 16; ++n)
#pragma unroll
        for (int e = 0; e < 4; ++e) accO[n][e] = 0.f;
    float m0 = 0.f, m1 = 0.f, l0 = 1.f, l1 = 1.f;

    const int aRow = 16 * w + (l & 15);
    const int aK8  = l >> 4;
    const int bRowL = l & 7;
    const int bK8   = (l >> 3) & 1;
    const int vRow0 = (l & 7) + 8 * ((l >> 3) & 1);

    const int nt = 2 * qi + 2;
    for (int j = 0; j < nt; ++j) {
        if (j + 1 < nt) {
            load_kv(j + 1, (j + 1) & 1);
            CP_COMMIT();
            CP_WAIT(1);
        } else {
            CP_WAIT(0);
        }
        __syncthreads();

        const uint32_t stb = sb + FSM_ST + (j & 1) * 65536;
        const uint32_t sKh = stb, sKl = stb + 16384;
        const uint32_t sVh = stb + 32768, sVl = stb + 49152;

        // ---- S = Q K^T (3-product) ----
        float accS[8][4];
#pragma unroll
        for (int n = 0; n < 8; ++n)
#pragma unroll
            for (int e = 0; e < 4; ++e) accS[n][e] = 0.f;

#pragma unroll
        for (int k = 0; k < 8; ++k) {
            uint32_t ah[4], al[4];
            int ac16 = 2 * k + aK8;
            uint32_t aoff = (uint32_t)(aRow * 256 + ((ac16 ^ (aRow & 7)) * 16));
            ldsm4(ah, sb + FSM_Q + aoff);
            ldsm4(al, sb + FSM_Q + 32768 + aoff);
#pragma unroll
            for (int n = 0; n < 8; ++n) {
                int brow = 8 * n + bRowL;
                int bc16 = 2 * k + bK8;
                uint32_t boff = (uint32_t)(brow * 256 + ((bc16 ^ (brow & 7)) * 16));
                uint32_t bh2[2], bl2[2];
                ldsm2(bh2, sKh + boff);
                ldsm2(bl2, sKl + boff);
                mma16816(accS[n], ah, bh2);
                mma16816(accS[n], ah, bl2);
                mma16816(accS[n], al, bh2);
            }
        }

        // ---- tanh cap + causal mask (fast math) ----
#pragma unroll
        for (int n = 0; n < 8; ++n)
#pragma unroll
            for (int e = 0; e < 4; ++e)
                accS[n][e] = cap50(accS[n][e]);

        if (j >= 2 * qi) {
            int r0 = 16 * w + (l >> 2);
            int cb = j * 64 - qi * 128 + 2 * (l & 3);
#pragma unroll
            for (int n = 0; n < 8; ++n) {
                int c = cb + 8 * n;
                if (c     > r0)     accS[n][0] = -50.f;
                if (c + 1 > r0)     accS[n][1] = -50.f;
                if (c     > r0 + 8) accS[n][2] = -50.f;
                if (c + 1 > r0 + 8) accS[n][3] = -50.f;
            }
        }

        // ---- online softmax ----
        float mx0 = -1e30f, mx1 = -1e30f;
#pragma unroll
        for (int n = 0; n < 8; ++n) {
            mx0 = fmaxf(mx0, fmaxf(accS[n][0], accS[n][1]));
            mx1 = fmaxf(mx1, fmaxf(accS[n][2], accS[n][3]));
        }
        mx0 = fmaxf(mx0, __shfl_xor_sync(0xffffffffu, mx0, 1));
        mx0 = fmaxf(mx0, __shfl_xor_sync(0xffffffffu, mx0, 2));
        mx1 = fmaxf(mx1, __shfl_xor_sync(0xffffffffu, mx1, 1));
        mx1 = fmaxf(mx1, __shfl_xor_sync(0xffffffffu, mx1, 2));
        float mn0 = fmaxf(m0, mx0), mn1 = fmaxf(m1, mx1);
        float sc0 = __expf(m0 - mn0), sc1 = __expf(m1 - mn1);
        float rs0 = 0.f, rs1 = 0.f;
#pragma unroll
        for (int n = 0; n < 8; ++n) {
            accS[n][0] = __expf(accS[n][0] - mn0); rs0 += accS[n][0];
            accS[n][1] = __expf(accS[n][1] - mn0); rs0 += accS[n][1];
            accS[n][2] = __expf(accS[n][2] - mn1); rs1 += accS[n][2];
            accS[n][3] = __expf(accS[n][3] - mn1); rs1 += accS[n][3];
        }
        rs0 += __shfl_xor_sync(0xffffffffu, rs0, 1);
        rs0 += __shfl_xor_sync(0xffffffffu, rs0, 2);
        rs1 += __shfl_xor_sync(0xffffffffu, rs1, 1);
        rs1 += __shfl_xor_sync(0xffffffffu, rs1, 2);
        l0 = l0 * sc0 + rs0;  m0 = mn0;
        l1 = l1 * sc1 + rs1;  m1 = mn1;
#pragma unroll
        for (int n = 0; n < 16; ++n) {
            accO[n][0] *= sc0; accO[n][1] *= sc0;
            accO[n][2] *= sc1; accO[n][3] *= sc1;
        }

        // ---- O += P V (2-product: P fp16 single, V 2-split) ----
#pragma unroll
        for (int kk = 0; kk < 4; ++kk) {
            uint32_t pa[4];
            pa[0] = pack2h(accS[2 * kk][0],     accS[2 * kk][1]);
            pa[1] = pack2h(accS[2 * kk][2],     accS[2 * kk][3]);
            pa[2] = pack2h(accS[2 * kk + 1][0], accS[2 * kk + 1][1]);
            pa[3] = pack2h(accS[2 * kk + 1][2], accS[2 * kk + 1][3]);
#pragma unroll
            for (int n = 0; n < 16; ++n) {
                int vrow = 16 * kk + vRow0;
                int vc16 = n ^ (vrow & 7);
                uint32_t voff = (uint32_t)(vrow * 256 + vc16 * 16);
                uint32_t vh2[2], vl2[2];
                ldsm2t(vh2, sVh + voff);
                ldsm2t(vl2, sVl + voff);
                mma16816(accO[n], pa, vh2);
                mma16816(accO[n], pa, vl2);
            }
        }
        __syncthreads();
    }

    // ---- write O as fp16 (hi only) in [b][s][h*128+d] layout ----
    float i0 = 1.f / l0, i1 = 1.f / l1;
    int row0 = qi * 128 + 16 * w + (l >> 2);
    size_t ob0 = ((size_t)b * Sc + row0) * Dc + h * HDc;
    size_t ob1 = ob0 + 8 * (size_t)Dc;
#pragma unroll
    for (int n = 0; n < 16; ++n) {
        int d = 8 * n + 2 * (l & 3);
        *(uint32_t*)&Ohi[ob0 + d] = pack2h(accO[n][0] * i0, accO[n][1] * i0);
        *(uint32_t*)&Ohi[ob1 + d] = pack2h(accO[n][2] * i1, accO[n][3] * i1);
    }
}

// ---------------------------------------------------------------------------
extern "C" void kernel_launch(void* const* d_in, const int* in_sizes, int n_in,
                              void* d_out, int out_size)
{
    const float* hidden = (const float*)d_in[0];
    const float* wq = (const float*)d_in[1];
    const float* wk = (const float*)d_in[2];
    const float* wv = (const float*)d_in[3];
    const float* wo = (const float*)d_in[4];
    float* out = (float*)d_out;

    float *q, *k, *v;
    __half *xhi, *xlo, *whiT, *wloT;
    __half *qhi, *qlo, *khi, *klo, *vhi, *vlo;
    cudaGetSymbolAddress((void**)&q, g_q);
    cudaGetSymbolAddress((void**)&k, g_k);
    cudaGetSymbolAddress((void**)&v, g_v);
    cudaGetSymbolAddress((void**)&xhi, g_xhi);
    cudaGetSymbolAddress((void**)&xlo, g_xlo);
    cudaGetSymbolAddress((void**)&whiT, g_whiT);
    cudaGetSymbolAddress((void**)&wloT, g_wloT);
    cudaGetSymbolAddress((void**)&qhi, g_qhi);
    cudaGetSymbolAddress((void**)&qlo, g_qlo);
    cudaGetSymbolAddress((void**)&khi, g_khi);
    cudaGetSymbolAddress((void**)&klo, g_klo);
    cudaGetSymbolAddress((void**)&vhi, g_vhi);
    cudaGetSymbolAddress((void**)&vlo, g_vlo);

    cudaFuncSetAttribute(gemm_hmma<3>, cudaFuncAttributeMaxDynamicSharedMemorySize, GSMEM_TOTAL);
    cudaFuncSetAttribute(gemm_hmma<2>, cudaFuncAttributeMaxDynamicSharedMemorySize, GSMEM_TOTAL);
    cudaFuncSetAttribute(flash_mma, cudaFuncAttributeMaxDynamicSharedMemorySize, FSM_TOT);

    // 1. splits
    conv_split<<<(TOTE / 4 + 255) / 256, 256>>>(hidden, xhi, xlo, TOTE / 4);
    conv_w_all<<<dim3(Dc / 32, Dc / 32, 4), dim3(32, 8)>>>(wq, wk, wv, wo, whiT, wloT);

    // 2. QKV projections (Q,K 3-product; V 2-product)
    dim3 ggrid(Dc / 64, MTOT / 128);     // (32, 32)
    gemm_hmma<3><<<ggrid, 256, GSMEM_TOTAL>>>(xhi, xlo, whiT + 0 * DD, wloT + 0 * DD, q);
    gemm_hmma<3><<<ggrid, 256, GSMEM_TOTAL>>>(xhi, xlo, whiT + 1 * DD, wloT + 1 * DD, k);
    gemm_hmma<2><<<ggrid, 256, GSMEM_TOTAL>>>(xhi, xlo, whiT + 2 * DD, wloT + 2 * DD, v);

    // 3. rotary + splits for attention
    rotary_split<<<(Bc * Sc * Hc * 64) / 256, 256>>>(q, k, qhi, qlo, khi, klo);
    v_split<<<(TOTE / 2) / 256, 256>>>(v, vhi, vlo);

    // 4. attention — writes xhi (fp16 O) for the output projection
    flash_mma<<<dim3(Sc / 128, Hc, Bc), 256, FSM_TOT>>>(qhi, qlo, khi, klo, vhi, vlo, xhi);

    // 5. output projection (2-product)
    gemm_hmma<2><<<ggrid, 256, GSMEM_TOTAL>>>(xhi, xlo, whiT + 3 * DD, wloT + 3 * DD, out);
}

// round 15
// speedup vs baseline: 5.6423x; 1.0604x over previous
#include <cuda_runtime.h>
#include <cuda_fp16.h>
#include <cstdint>
#include <math.h>

// Problem dims
#define Bc  2
#define Sc  2048
#define Dc  2048
#define Hc  16
#define HDc 128
#define MTOT (Bc * Sc)            // 4096
#define TOTE (Bc * Sc * Dc)       // 8388608
#define DD   (Dc * Dc)            // 4194304

// ---------------------------------------------------------------------------
// Scratch (__device__ globals: allocation-free rule)
// ---------------------------------------------------------------------------
__device__ float g_q[TOTE];
__device__ float g_k[TOTE];
__device__ float g_v[TOTE];
__device__ __half g_xhi[TOTE];      // GEMM activation splits (hidden, then O)
__device__ __half g_xlo[TOTE];
__device__ __half g_whiT[4 * DD];   // W^T splits for wq,wk,wv,wo  [n][k]
__device__ __half g_wloT[4 * DD];
// attention operands, [b][h][s][128] layout
__device__ __half g_qhi[TOTE], g_qlo[TOTE];
__device__ __half g_khi[TOTE], g_klo[TOTE];
__device__ __half g_vhi[TOTE], g_vlo[TOTE];

// ---------------------------------------------------------------------------
// PTX helpers (baseline ISA: mma.sync / ldmatrix / cp.async — sm_103-safe)
// ---------------------------------------------------------------------------
__device__ __forceinline__ uint32_t smem_u32(const void* p) {
    uint32_t a;
    asm("{ .reg .u64 t; cvta.to.shared.u64 t, %1; cvt.u32.u64 %0, t; }" : "=r"(a) : "l"(p));
    return a;
}
__device__ __forceinline__ void ldsm4(uint32_t* r, uint32_t addr) {
    asm volatile("ldmatrix.sync.aligned.m8n8.x4.shared.b16 {%0,%1,%2,%3}, [%4];"
                 : "=r"(r[0]), "=r"(r[1]), "=r"(r[2]), "=r"(r[3]) : "r"(addr));
}
__device__ __forceinline__ void ldsm4t(uint32_t* r, uint32_t addr) {
    asm volatile("ldmatrix.sync.aligned.m8n8.x4.trans.shared.b16 {%0,%1,%2,%3}, [%4];"
                 : "=r"(r[0]), "=r"(r[1]), "=r"(r[2]), "=r"(r[3]) : "r"(addr));
}
__device__ __forceinline__ void mma16816(float* c, const uint32_t* a, const uint32_t* b) {
    asm volatile("mma.sync.aligned.m16n8k16.row.col.f32.f16.f16.f32 "
                 "{%0,%1,%2,%3}, {%4,%5,%6,%7}, {%8,%9}, {%0,%1,%2,%3};"
                 : "+f"(c[0]), "+f"(c[1]), "+f"(c[2]), "+f"(c[3])
                 : "r"(a[0]), "r"(a[1]), "r"(a[2]), "r"(a[3]), "r"(b[0]), "r"(b[1]));
}
__device__ __forceinline__ void cp16(uint32_t smem, const void* g) {
    asm volatile("cp.async.cg.shared.global [%0], [%1], 16;" :: "r"(smem), "l"(g));
}
#define CP_COMMIT() asm volatile("cp.async.commit_group;" ::: "memory")
#define CP_WAIT(N)  asm volatile("cp.async.wait_group %0;" :: "n"(N) : "memory")

__device__ __forceinline__ void splitpack(float x, float y, uint32_t& hi, uint32_t& lo) {
    __half hx = __float2half(x), hy = __float2half(y);
    float lx = x - __half2float(hx), ly = y - __half2float(hy);
    __half2 hv(hx, hy);
    __half2 lv(__float2half(lx), __float2half(ly));
    hi = *(uint32_t*)&hv;
    lo = *(uint32_t*)&lv;
}
__device__ __forceinline__ uint32_t pack2h(float x, float y) {
    __half2 h(__float2half(x), __float2half(y));
    return *(uint32_t*)&h;
}
// 50*tanh(s/50) via __expf; graceful at large |s|
__device__ __forceinline__ float cap50(float s) {
    float e = __expf(s * 0.04f);
    return 50.f * (1.f - 2.f / (e + 1.f));
}

// ---------------------------------------------------------------------------
// fp32 -> fp16 hi/lo split (elementwise, float4 vectorized)
// ---------------------------------------------------------------------------
__global__ void conv_split(const float* __restrict__ in,
                           __half* __restrict__ hi, __half* __restrict__ lo, int n4)
{
    int i = blockIdx.x * blockDim.x + threadIdx.x;
    if (i >= n4) return;
    float4 v = ((const float4*)in)[i];
    uint32_t h0, l0, h1, l1;
    splitpack(v.x, v.y, h0, l0);
    splitpack(v.z, v.w, h1, l1);
    uint32_t* hp = (uint32_t*)hi;
    uint32_t* lp = (uint32_t*)lo;
    hp[2 * i] = h0; hp[2 * i + 1] = h1;
    lp[2 * i] = l0; lp[2 * i + 1] = l1;
}

// ---------------------------------------------------------------------------
// All 4 weights: W[k][n] fp32 -> W^T[n][k] fp16 hi/lo (z = weight index)
// ---------------------------------------------------------------------------
__global__ void conv_w_all(const float* __restrict__ w0, const float* __restrict__ w1,
                           const float* __restrict__ w2, const float* __restrict__ w3,
                           __half* __restrict__ hiT, __half* __restrict__ loT)
{
    __shared__ float tile[32][33];
    const float* w = (blockIdx.z == 0) ? w0 : (blockIdx.z == 1) ? w1
                   : (blockIdx.z == 2) ? w2 : w3;
    __half* hO = hiT + (size_t)blockIdx.z * DD;
    __half* lO = loT + (size_t)blockIdx.z * DD;
    int n0 = blockIdx.x * 32, k0 = blockIdx.y * 32;
    int tx = threadIdx.x, ty = threadIdx.y;   // 32 x 8
#pragma unroll
    for (int i = 0; i < 4; ++i)
        tile[ty + i * 8][tx] = w[(size_t)(k0 + ty + i * 8) * Dc + n0 + tx];
    __syncthreads();
#pragma unroll
    for (int i = 0; i < 4; ++i) {
        float v = tile[tx][ty + i * 8];
        __half h = __float2half(v);
        __half l = __float2half(v - __half2float(h));
        size_t oidx = (size_t)(n0 + ty + i * 8) * Dc + k0 + tx;
        hO[oidx] = h;
        lO[oidx] = l;
    }
}

// ---------------------------------------------------------------------------
// HMMA fp16 split GEMM: C[4096x2048] = A @ W
// CTA tile 128x64, 8 warps (4x2), warp tile 32x32 — 3 CTAs/SM.
// B fragments fetched as paired ldsm4 (2 n-tiles per instruction).
// NP=3: Ah*Bh + Ah*Bl + Al*Bh. NP=2: Ah*Bh + Ah*Bl.
// ---------------------------------------------------------------------------
#define GKT 32
#define ROWB 80                          // 32 halfs + 8 pad
#define TILE_A_B (128 * ROWB)            // 10240
#define TILE_B_B (64 * ROWB)             // 5120
#define OFF_AHI 0
#define OFF_ALO TILE_A_B
#define OFF_BHI (2 * TILE_A_B)
#define OFF_BLO (2 * TILE_A_B + TILE_B_B)
#define STAGE_B (2 * TILE_A_B + 2 * TILE_B_B)  // 30720
#define GSMEM_TOTAL (2 * STAGE_B)              // 61440

template<int NP>
__global__ __launch_bounds__(256, 3) void gemm_hmma(
    const __half* __restrict__ Ahi, const __half* __restrict__ Alo,
    const __half* __restrict__ BhiT, const __half* __restrict__ BloT,
    float* __restrict__ C)
{
    extern __shared__ __align__(128) char smem[];
    const uint32_t sb = smem_u32(smem);
    const int t   = threadIdx.x;
    const int l   = t & 31;
    const int wid = t >> 5;
    const int wm  = wid >> 1;            // 0..3 -> m offset wm*32
    const int wn  = wid & 1;             // 0..1 -> n offset wn*32
    const int m0  = blockIdx.y * 128;
    const int n0  = blockIdx.x * 64;

    // A ldsm4 lane address (16 rows x 16 halves per warp m-tile)
    const int arow = (l & 7) + ((l >> 3) & 1) * 8;
    const int ak8  = (l >> 4);
    const uint32_t aoff = (uint32_t)((wm * 32 + arow) * ROWB + ak8 * 16);
    // B paired ldsm4: lane group l>>3 -> matrix; rows span two n-tiles (16)
    const int bprow = (l >> 4) * 8 + (l & 7);       // row within 16-row pair
    const int bpk8  = (l >> 3) & 1;                 // k-chunk of the matrix
    const uint32_t bpoff = (uint32_t)((wn * 32 + bprow) * ROWB + bpk8 * 16);

    float acc[2][4][4];
#pragma unroll
    for (int i = 0; i < 2; ++i)
#pragma unroll
        for (int j = 0; j < 4; ++j)
#pragma unroll
            for (int u = 0; u < 4; ++u) acc[i][j][u] = 0.f;

    // chunk map: 1536 16B chunks/stage (NP3): [0,512) Ahi, [512,1024) Alo,
    // [1024,1280) Bhi, [1280,1536) Blo. i=2,3 cover Alo exactly -> skipped NP2.
    auto load_tiles = [&](int kt, int s) {
        const uint32_t st = sb + s * STAGE_B;
#pragma unroll
        for (int i = 0; i < 6; ++i) {
            if (NP == 2 && (i == 2 || i == 3)) continue;
            int c = t + 256 * i;
            const __half* src;
            uint32_t toff;
            int rbase, local;
            if (c < 512)        { src = Ahi;  toff = OFF_AHI; rbase = m0; local = c; }
            else if (c < 1024)  { src = Alo;  toff = OFF_ALO; rbase = m0; local = c - 512; }
            else if (c < 1280)  { src = BhiT; toff = OFF_BHI; rbase = n0; local = c - 1024; }
            else                { src = BloT; toff = OFF_BLO; rbase = n0; local = c - 1280; }
            int row = local >> 2, ch = local & 3;
            cp16(st + toff + row * ROWB + ch * 16,
                 src + (size_t)(rbase + row) * Dc + kt * GKT + ch * 8);
        }
    };

    load_tiles(0, 0);
    CP_COMMIT();

    for (int kt = 0; kt < Dc / GKT; ++kt) {
        if (kt + 1 < Dc / GKT) {
            load_tiles(kt + 1, (kt + 1) & 1);
            CP_COMMIT();
            CP_WAIT(1);
        } else {
            CP_WAIT(0);
        }
        __syncthreads();

        const uint32_t st = sb + (kt & 1) * STAGE_B;

#pragma unroll
        for (int ks = 0; ks < 2; ++ks) {
            uint32_t ah[2][4], al[2][4], bh[2][4], bl[2][4];
#pragma unroll
            for (int mt = 0; mt < 2; ++mt) {
                ldsm4(ah[mt], st + OFF_AHI + aoff + mt * (16 * ROWB) + ks * 32);
                if (NP == 3)
                    ldsm4(al[mt], st + OFF_ALO + aoff + mt * (16 * ROWB) + ks * 32);
            }
#pragma unroll
            for (int p = 0; p < 2; ++p) {
                ldsm4(bh[p], st + OFF_BHI + bpoff + p * (16 * ROWB) + ks * 32);
                ldsm4(bl[p], st + OFF_BLO + bpoff + p * (16 * ROWB) + ks * 32);
            }
#pragma unroll
            for (int mt = 0; mt < 2; ++mt)
#pragma unroll
                for (int nt = 0; nt < 4; ++nt)
                    mma16816(acc[mt][nt], ah[mt], &bh[nt >> 1][(nt & 1) * 2]);
#pragma unroll
            for (int mt = 0; mt < 2; ++mt)
#pragma unroll
                for (int nt = 0; nt < 4; ++nt)
                    mma16816(acc[mt][nt], ah[mt], &bl[nt >> 1][(nt & 1) * 2]);
            if (NP == 3) {
#pragma unroll
                for (int mt = 0; mt < 2; ++mt)
#pragma unroll
                    for (int nt = 0; nt < 4; ++nt)
                        mma16816(acc[mt][nt], al[mt], &bh[nt >> 1][(nt & 1) * 2]);
            }
        }
        __syncthreads();
    }

    const int erow = m0 + wm * 32 + (l >> 2);
    const int ecol = n0 + wn * 32 + (l & 3) * 2;
#pragma unroll
    for (int mt = 0; mt < 2; ++mt)
#pragma unroll
        for (int nt = 0; nt < 4; ++nt) {
            *(float2*)&C[(size_t)(erow + mt * 16) * Dc + ecol + nt * 8] =
                make_float2(acc[mt][nt][0], acc[mt][nt][1]);
            *(float2*)&C[(size_t)(erow + mt * 16 + 8) * Dc + ecol + nt * 8] =
                make_float2(acc[mt][nt][2], acc[mt][nt][3]);
        }
}

// ---------------------------------------------------------------------------
// Rotary + fp16 hi/lo split: fp32 [b][s][h*128+d] -> fp16 [b][h][s][128]
// ---------------------------------------------------------------------------
__global__ void rotary_split(const float* __restrict__ q, const float* __restrict__ k,
                             __half* __restrict__ qhi, __half* __restrict__ qlo,
                             __half* __restrict__ khi, __half* __restrict__ klo)
{
    int idx = blockIdx.x * blockDim.x + threadIdx.x;
    if (idx >= Bc * Sc * Hc * 64) return;
    int j = idx & 63;
    int h = (idx >> 6) & (Hc - 1);
    int s = (idx >> 10) & (Sc - 1);
    int b = idx >> 21;

    float inv_freq = 1.0f / powf(10000.0f, (float)j * (1.0f / 64.0f));
    float sn, cs;
    sincosf((float)s * inv_freq, &sn, &cs);

    size_t ib = ((size_t)(b * Sc + s)) * Dc + h * HDc + j;
    size_t ob = ((size_t)((b * Hc + h) * Sc + s)) * HDc + j;

    float q1 = q[ib], q2 = q[ib + 64];
    float qa = q1 * cs - q2 * sn;
    float qb = q2 * cs + q1 * sn;
    float k1 = k[ib], k2 = k[ib + 64];
    float ka = k1 * cs - k2 * sn;
    float kb = k2 * cs + k1 * sn;

    __half hqa = __float2half(qa), hqb = __float2half(qb);
    __half hka = __float2half(ka), hkb = __float2half(kb);
    qhi[ob] = hqa;      qhi[ob + 64] = hqb;
    qlo[ob] = __float2half(qa - __half2float(hqa));
    qlo[ob + 64] = __float2half(qb - __half2float(hqb));
    khi[ob] = hka;      khi[ob + 64] = hkb;
    klo[ob] = __float2half(ka - __half2float(hka));
    klo[ob + 64] = __float2half(kb - __half2float(hkb));
}

// ---------------------------------------------------------------------------
// V split: fp32 [b][s][h*128+d] -> fp16 hi/lo [b][h][s][128]
// ---------------------------------------------------------------------------
__global__ void v_split(const float* __restrict__ v,
                        __half* __restrict__ vhi, __half* __restrict__ vlo)
{
    int idx = blockIdx.x * blockDim.x + threadIdx.x;
    if (idx >= TOTE / 2) return;
    int d2 = idx & 63;
    int h = (idx >> 6) & (Hc - 1);
    int s = (idx >> 10) & (Sc - 1);
    int b = idx >> 21;
    const float2 vv = *(const float2*)&v[((size_t)(b * Sc + s)) * Dc + h * HDc + d2 * 2];
    uint32_t hp, lp;
    splitpack(vv.x, vv.y, hp, lp);
    size_t ob = ((size_t)((b * Hc + h) * Sc + s)) * HDc + d2 * 2;
    *(uint32_t*)&vhi[ob] = hp;
    *(uint32_t*)&vlo[ob] = lp;
}

// ---------------------------------------------------------------------------
// Flash attention on HMMA: QK 3-product, PV 2-product (P single fp16),
// causal + tanh cap + Lingvo softmax (phantom 0-logit: m=0, l=1).
// CTA: 128 q rows x KV tiles of 64; 8 warps; 2-stage cp.async K/V.
// K and V fragments fetched as paired ldsm4 / ldsm4.trans.
// ---------------------------------------------------------------------------
#define FSM_Q   0
#define FSM_ST  65536
#define FSM_TOT (65536 + 2 * 65536)      // 196608 = 192KB

__global__ __launch_bounds__(256) void flash_mma(
    const __half* __restrict__ qhi, const __half* __restrict__ qlo,
    const __half* __restrict__ khi, const __half* __restrict__ klo,
    const __half* __restrict__ vhi, const __half* __restrict__ vlo,
    __half* __restrict__ Ohi)
{
    extern __shared__ __align__(128) char smem[];
    const uint32_t sb = smem_u32(smem);
    const int t = threadIdx.x, l = t & 31, w = t >> 5;
    const int qi = (Sc / 128 - 1) - blockIdx.x;        // heavy CTAs first
    const int h = blockIdx.y, b = blockIdx.z;
    const size_t hb = (size_t)(b * Hc + h) * Sc * HDc;

#pragma unroll
    for (int i = 0; i < 8; ++i) {
        int c = t + 256 * i;
        int row = c >> 4, c16 = c & 15;
        uint32_t dst = (uint32_t)(row * 256 + ((c16 ^ (row & 7)) * 16));
        size_t src = hb + (size_t)(qi * 128 + row) * HDc + c16 * 8;
        cp16(sb + FSM_Q + dst, qhi + src);
        cp16(sb + FSM_Q + 32768 + dst, qlo + src);
    }
    auto load_kv = [&](int j, int st) {
        uint32_t stb = sb + FSM_ST + st * 65536;
#pragma unroll
        for (int i = 0; i < 4; ++i) {
            int c = t + 256 * i;
            int row = c >> 4, c16 = c & 15;
            uint32_t dst = (uint32_t)(row * 256 + ((c16 ^ (row & 7)) * 16));
            size_t src = hb + (size_t)(j * 64 + row) * HDc + c16 * 8;
            cp16(stb + dst,         khi + src);
            cp16(stb + 16384 + dst, klo + src);
            cp16(stb + 32768 + dst, vhi + src);
            cp16(stb + 49152 + dst, vlo + src);
        }
    };
    load_kv(0, 0);
    CP_COMMIT();

    float accO[16][4];
#pragma unroll
    for (int n = 0; n < 16; ++n)
#pragma unroll
        for (int e = 0; e < 4; ++e) accO[n][e] = 0.f;
    float m0 = 0.f, m1 = 0.f, l0 = 1.f, l1 = 1.f;

    // Q ldsm4 lane address
    const int aRow = 16 * w + (l & 15);
    const int aK8  = l >> 4;
    // K paired ldsm4: 16 rows (2 n-tiles) per instruction
    const int kRowL = (l >> 4) * 8 + (l & 7);
    const int kK8   = (l >> 3) & 1;
    // V paired ldsm4.trans: 16 k-rows, 2 d-chunks per instruction
    const int vRow0 = (l & 7) + 8 * ((l >> 3) & 1);
    const int vC    = l >> 4;                        // which d-chunk of the pair

    const int nt = 2 * qi + 2;
    for (int j = 0; j < nt; ++j) {
        if (j + 1 < nt) {
            load_kv(j + 1, (j + 1) & 1);
            CP_COMMIT();
            CP_WAIT(1);
        } else {
            CP_WAIT(0);
        }
        __syncthreads();

        const uint32_t stb = sb + FSM_ST + (j & 1) * 65536;
        const uint32_t sKh = stb, sKl = stb + 16384;
        const uint32_t sVh = stb + 32768, sVl = stb + 49152;

        // ---- S = Q K^T (3-product) ----
        float accS[8][4];
#pragma unroll
        for (int n = 0; n < 8; ++n)
#pragma unroll
            for (int e = 0; e < 4; ++e) accS[n][e] = 0.f;

#pragma unroll
        for (int k = 0; k < 8; ++k) {
            uint32_t ah[4], al[4];
            int ac16 = 2 * k + aK8;
            uint32_t aoff = (uint32_t)(aRow * 256 + ((ac16 ^ (aRow & 7)) * 16));
            ldsm4(ah, sb + FSM_Q + aoff);
            ldsm4(al, sb + FSM_Q + 32768 + aoff);
#pragma unroll
            for (int p = 0; p < 4; ++p) {
                int krow = 16 * p + kRowL;
                int kc16 = 2 * k + kK8;
                uint32_t boff = (uint32_t)(krow * 256 + ((kc16 ^ (krow & 7)) * 16));
                uint32_t bh4[4], bl4[4];
                ldsm4(bh4, sKh + boff);
                ldsm4(bl4, sKl + boff);
                mma16816(accS[2 * p],     ah, &bh4[0]);
                mma16816(accS[2 * p + 1], ah, &bh4[2]);
                mma16816(accS[2 * p],     ah, &bl4[0]);
                mma16816(accS[2 * p + 1], ah, &bl4[2]);
                mma16816(accS[2 * p],     al, &bh4[0]);
                mma16816(accS[2 * p + 1], al, &bh4[2]);
            }
        }

        // ---- tanh cap + causal mask (fast math) ----
#pragma unroll
        for (int n = 0; n < 8; ++n)
#pragma unroll
            for (int e = 0; e < 4; ++e)
                accS[n][e] = cap50(accS[n][e]);

        if (j >= 2 * qi) {
            int r0 = 16 * w + (l >> 2);
            int cb = j * 64 - qi * 128 + 2 * (l & 3);
#pragma unroll
            for (int n = 0; n < 8; ++n) {
                int c = cb + 8 * n;
                if (c     > r0)     accS[n][0] = -50.f;
                if (c + 1 > r0)     accS[n][1] = -50.f;
                if (c     > r0 + 8) accS[n][2] = -50.f;
                if (c + 1 > r0 + 8) accS[n][3] = -50.f;
            }
        }

        // ---- online softmax ----
        float mx0 = -1e30f, mx1 = -1e30f;
#pragma unroll
        for (int n = 0; n < 8; ++n) {
            mx0 = fmaxf(mx0, fmaxf(accS[n][0], accS[n][1]));
            mx1 = fmaxf(mx1, fmaxf(accS[n][2], accS[n][3]));
        }
        mx0 = fmaxf(mx0, __shfl_xor_sync(0xffffffffu, mx0, 1));
        mx0 = fmaxf(mx0, __shfl_xor_sync(0xffffffffu, mx0, 2));
        mx1 = fmaxf(mx1, __shfl_xor_sync(0xffffffffu, mx1, 1));
        mx1 = fmaxf(mx1, __shfl_xor_sync(0xffffffffu, mx1, 2));
        float mn0 = fmaxf(m0, mx0), mn1 = fmaxf(m1, mx1);
        float sc0 = __expf(m0 - mn0), sc1 = __expf(m1 - mn1);
        float rs0 = 0.f, rs1 = 0.f;
#pragma unroll
        for (int n = 0; n < 8; ++n) {
            accS[n][0] = __expf(accS[n][0] - mn0); rs0 += accS[n][0];
            accS[n][1] = __expf(accS[n][1] - mn0); rs0 += accS[n][1];
            accS[n][2] = __expf(accS[n][2] - mn1); rs1 += accS[n][2];
            accS[n][3] = __expf(accS[n][3] - mn1); rs1 += accS[n][3];
        }
        rs0 += __shfl_xor_sync(0xffffffffu, rs0, 1);
        rs0 += __shfl_xor_sync(0xffffffffu, rs0, 2);
        rs1 += __shfl_xor_sync(0xffffffffu, rs1, 1);
        rs1 += __shfl_xor_sync(0xffffffffu, rs1, 2);
        l0 = l0 * sc0 + rs0;  m0 = mn0;
        l1 = l1 * sc1 + rs1;  m1 = mn1;
#pragma unroll
        for (int n = 0; n < 16; ++n) {
            accO[n][0] *= sc0; accO[n][1] *= sc0;
            accO[n][2] *= sc1; accO[n][3] *= sc1;
        }

        // ---- O += P V (2-product: P fp16 single, V 2-split, paired ldsm4t) ----
#pragma unroll
        for (int kk = 0; kk < 4; ++kk) {
            uint32_t pa[4];
            pa[0] = pack2h(accS[2 * kk][0],     accS[2 * kk][1]);
            pa[1] = pack2h(accS[2 * kk][2],     accS[2 * kk][3]);
            pa[2] = pack2h(accS[2 * kk + 1][0], accS[2 * kk + 1][1]);
            pa[3] = pack2h(accS[2 * kk + 1][2], accS[2 * kk + 1][3]);
            int vrow = 16 * kk + vRow0;
#pragma unroll
            for (int np = 0; np < 8; ++np) {
                int vc16 = (2 * np + vC) ^ (vrow & 7);
                uint32_t voff = (uint32_t)(vrow * 256 + vc16 * 16);
                uint32_t vh4[4], vl4[4];
                ldsm4t(vh4, sVh + voff);
                ldsm4t(vl4, sVl + voff);
                mma16816(accO[2 * np],     pa, &vh4[0]);
                mma16816(accO[2 * np + 1], pa, &vh4[2]);
                mma16816(accO[2 * np],     pa, &vl4[0]);
                mma16816(accO[2 * np + 1], pa, &vl4[2]);
            }
        }
        __syncthreads();
    }

    // ---- write O as fp16 (hi only) in [b][s][h*128+d] layout ----
    float i0 = 1.f / l0, i1 = 1.f / l1;
    int row0 = qi * 128 + 16 * w + (l >> 2);
    size_t ob0 = ((size_t)b * Sc + row0) * Dc + h * HDc;
    size_t ob1 = ob0 + 8 * (size_t)Dc;
#pragma unroll
    for (int n = 0; n < 16; ++n) {
        int d = 8 * n + 2 * (l & 3);
        *(uint32_t*)&Ohi[ob0 + d] = pack2h(accO[n][0] * i0, accO[n][1] * i0);
        *(uint32_t*)&Ohi[ob1 + d] = pack2h(accO[n][2] * i1, accO[n][3] * i1);
    }
}

// ---------------------------------------------------------------------------
extern "C" void kernel_launch(void* const* d_in, const int* in_sizes, int n_in,
                              void* d_out, int out_size)
{
    const float* hidden = (const float*)d_in[0];
    const float* wq = (const float*)d_in[1];
    const float* wk = (const float*)d_in[2];
    const float* wv = (const float*)d_in[3];
    const float* wo = (const float*)d_in[4];
    float* out = (float*)d_out;

    float *q, *k, *v;
    __half *xhi, *xlo, *whiT, *wloT;
    __half *qhi, *qlo, *khi, *klo, *vhi, *vlo;
    cudaGetSymbolAddress((void**)&q, g_q);
    cudaGetSymbolAddress((void**)&k, g_k);
    cudaGetSymbolAddress((void**)&v, g_v);
    cudaGetSymbolAddress((void**)&xhi, g_xhi);
    cudaGetSymbolAddress((void**)&xlo, g_xlo);
    cudaGetSymbolAddress((void**)&whiT, g_whiT);
    cudaGetSymbolAddress((void**)&wloT, g_wloT);
    cudaGetSymbolAddress((void**)&qhi, g_qhi);
    cudaGetSymbolAddress((void**)&qlo, g_qlo);
    cudaGetSymbolAddress((void**)&khi, g_khi);
    cudaGetSymbolAddress((void**)&klo, g_klo);
    cudaGetSymbolAddress((void**)&vhi, g_vhi);
    cudaGetSymbolAddress((void**)&vlo, g_vlo);

    cudaFuncSetAttribute(gemm_hmma<3>, cudaFuncAttributeMaxDynamicSharedMemorySize, GSMEM_TOTAL);
    cudaFuncSetAttribute(gemm_hmma<2>, cudaFuncAttributeMaxDynamicSharedMemorySize, GSMEM_TOTAL);
    cudaFuncSetAttribute(flash_mma, cudaFuncAttributeMaxDynamicSharedMemorySize, FSM_TOT);

    // 1. splits
    conv_split<<<(TOTE / 4 + 255) / 256, 256>>>(hidden, xhi, xlo, TOTE / 4);
    conv_w_all<<<dim3(Dc / 32, Dc / 32, 4), dim3(32, 8)>>>(wq, wk, wv, wo, whiT, wloT);

    // 2. QKV projections (Q,K 3-product; V 2-product)
    dim3 ggrid(Dc / 64, MTOT / 128);     // (32, 32)
    gemm_hmma<3><<<ggrid, 256, GSMEM_TOTAL>>>(xhi, xlo, whiT + 0 * DD, wloT + 0 * DD, q);
    gemm_hmma<3><<<ggrid, 256, GSMEM_TOTAL>>>(xhi, xlo, whiT + 1 * DD, wloT + 1 * DD, k);
    gemm_hmma<2><<<ggrid, 256, GSMEM_TOTAL>>>(xhi, xlo, whiT + 2 * DD, wloT + 2 * DD, v);

    // 3. rotary + splits for attention
    rotary_split<<<(Bc * Sc * Hc * 64) / 256, 256>>>(q, k, qhi, qlo, khi, klo);
    v_split<<<(TOTE / 2) / 256, 256>>>(v, vhi, vlo);

    // 4. attention — writes xhi (fp16 O) for the output projection
    flash_mma<<<dim3(Sc / 128, Hc, Bc), 256, FSM_TOT>>>(qhi, qlo, khi, klo, vhi, vlo, xhi);

    // 5. output projection (2-product)
    gemm_hmma<2><<<ggrid, 256, GSMEM_TOTAL>>>(xhi, xlo, whiT + 3 * DD, wloT + 3 * DD, out);
}

// round 17
// speedup vs baseline: 6.7020x; 1.1878x over previous
#include <cuda_runtime.h>
#include <cuda_fp16.h>
#include <cstdint>
#include <math.h>

// Problem dims
#define Bc  2
#define Sc  2048
#define Dc  2048
#define Hc  16
#define HDc 128
#define MTOT (Bc * Sc)            // 4096
#define TOTE (Bc * Sc * Dc)       // 8388608
#define DD   (Dc * Dc)            // 4194304

// ---------------------------------------------------------------------------
// Scratch (__device__ globals: allocation-free rule)
// ---------------------------------------------------------------------------
__device__ float g_q[TOTE];
__device__ float g_k[TOTE];
__device__ float g_v[TOTE];
__device__ __half g_xhi[TOTE];      // GEMM activation splits (hidden, then O)
__device__ __half g_xlo[TOTE];
__device__ __half g_whiT[4 * DD];   // W^T splits for wq,wk,wv,wo  [n][k]
__device__ __half g_wloT[4 * DD];
// attention operands, [b][h][s][128] layout
__device__ __half g_qhi[TOTE], g_qlo[TOTE];
__device__ __half g_khi[TOTE], g_klo[TOTE];
__device__ __half g_vhi[TOTE], g_vlo[TOTE];

// ---------------------------------------------------------------------------
// PTX helpers (baseline ISA: mma.sync / ldmatrix / cp.async — sm_103-safe)
// ---------------------------------------------------------------------------
__device__ __forceinline__ uint32_t smem_u32(const void* p) {
    uint32_t a;
    asm("{ .reg .u64 t; cvta.to.shared.u64 t, %1; cvt.u32.u64 %0, t; }" : "=r"(a) : "l"(p));
    return a;
}
__device__ __forceinline__ void ldsm4(uint32_t* r, uint32_t addr) {
    asm volatile("ldmatrix.sync.aligned.m8n8.x4.shared.b16 {%0,%1,%2,%3}, [%4];"
                 : "=r"(r[0]), "=r"(r[1]), "=r"(r[2]), "=r"(r[3]) : "r"(addr));
}
__device__ __forceinline__ void ldsm4t(uint32_t* r, uint32_t addr) {
    asm volatile("ldmatrix.sync.aligned.m8n8.x4.trans.shared.b16 {%0,%1,%2,%3}, [%4];"
                 : "=r"(r[0]), "=r"(r[1]), "=r"(r[2]), "=r"(r[3]) : "r"(addr));
}
__device__ __forceinline__ void mma16816(float* c, const uint32_t* a, const uint32_t* b) {
    asm volatile("mma.sync.aligned.m16n8k16.row.col.f32.f16.f16.f32 "
                 "{%0,%1,%2,%3}, {%4,%5,%6,%7}, {%8,%9}, {%0,%1,%2,%3};"
                 : "+f"(c[0]), "+f"(c[1]), "+f"(c[2]), "+f"(c[3])
                 : "r"(a[0]), "r"(a[1]), "r"(a[2]), "r"(a[3]), "r"(b[0]), "r"(b[1]));
}
__device__ __forceinline__ void cp16(uint32_t smem, const void* g) {
    asm volatile("cp.async.cg.shared.global [%0], [%1], 16;" :: "r"(smem), "l"(g));
}
#define CP_COMMIT() asm volatile("cp.async.commit_group;" ::: "memory")
#define CP_WAIT(N)  asm volatile("cp.async.wait_group %0;" :: "n"(N) : "memory")

__device__ __forceinline__ void splitpack(float x, float y, uint32_t& hi, uint32_t& lo) {
    __half hx = __float2half(x), hy = __float2half(y);
    float lx = x - __half2float(hx), ly = y - __half2float(hy);
    __half2 hv(hx, hy);
    __half2 lv(__float2half(lx), __float2half(ly));
    hi = *(uint32_t*)&hv;
    lo = *(uint32_t*)&lv;
}
__device__ __forceinline__ uint32_t pack2h(float x, float y) {
    __half2 h(__float2half(x), __float2half(y));
    return *(uint32_t*)&h;
}
// 50*tanh(s/50) via __expf; graceful at large |s|
__device__ __forceinline__ float cap50(float s) {
    float e = __expf(s * 0.04f);
    return 50.f * (1.f - 2.f / (e + 1.f));
}
// packed 64B-row swizzle: two 64B logical rows per 128B smem row, 16B chunks
__device__ __forceinline__ uint32_t sw64(int row, int c) {
    return (uint32_t)((row >> 1) * 128 + (((c | ((row & 1) << 2)) ^ ((row >> 1) & 7)) << 4));
}

// ---------------------------------------------------------------------------
// fp32 -> fp16 hi/lo split (elementwise, float4 vectorized)
// ---------------------------------------------------------------------------
__global__ void conv_split(const float* __restrict__ in,
                           __half* __restrict__ hi, __half* __restrict__ lo, int n4)
{
    int i = blockIdx.x * blockDim.x + threadIdx.x;
    if (i >= n4) return;
    float4 v = ((const float4*)in)[i];
    uint32_t h0, l0, h1, l1;
    splitpack(v.x, v.y, h0, l0);
    splitpack(v.z, v.w, h1, l1);
    uint32_t* hp = (uint32_t*)hi;
    uint32_t* lp = (uint32_t*)lo;
    hp[2 * i] = h0; hp[2 * i + 1] = h1;
    lp[2 * i] = l0; lp[2 * i + 1] = l1;
}

// ---------------------------------------------------------------------------
// All 4 weights: W[k][n] fp32 -> W^T[n][k] fp16 hi/lo (z = weight index)
// ---------------------------------------------------------------------------
__global__ void conv_w_all(const float* __restrict__ w0, const float* __restrict__ w1,
                           const float* __restrict__ w2, const float* __restrict__ w3,
                           __half* __restrict__ hiT, __half* __restrict__ loT)
{
    __shared__ float tile[32][33];
    const float* w = (blockIdx.z == 0) ? w0 : (blockIdx.z == 1) ? w1
                   : (blockIdx.z == 2) ? w2 : w3;
    __half* hO = hiT + (size_t)blockIdx.z * DD;
    __half* lO = loT + (size_t)blockIdx.z * DD;
    int n0 = blockIdx.x * 32, k0 = blockIdx.y * 32;
    int tx = threadIdx.x, ty = threadIdx.y;   // 32 x 8
#pragma unroll
    for (int i = 0; i < 4; ++i)
        tile[ty + i * 8][tx] = w[(size_t)(k0 + ty + i * 8) * Dc + n0 + tx];
    __syncthreads();
#pragma unroll
    for (int i = 0; i < 4; ++i) {
        float v = tile[tx][ty + i * 8];
        __half h = __float2half(v);
        __half l = __float2half(v - __half2float(h));
        size_t oidx = (size_t)(n0 + ty + i * 8) * Dc + k0 + tx;
        hO[oidx] = h;
        lO[oidx] = l;
    }
}

// ---------------------------------------------------------------------------
// HMMA fp16 split GEMM: C[4096x2048] = A @ W
// CTA tile 128x64, 8 warps (4x2), warp tile 32x32 — 3 CTAs/SM.
// Packed swizzled smem (no padding), 3-stage cp.async, ONE barrier per ktile.
// NP=3: Ah*Bh + Ah*Bl + Al*Bh. NP=2: Ah*Bh + Ah*Bl.
// ---------------------------------------------------------------------------
#define GKT 32
#define TILE_A_B 8192                    // 128 rows x 64B packed
#define TILE_B_B 4096                    // 64 rows x 64B packed
#define OFF_AHI 0
#define OFF_ALO TILE_A_B
#define OFF_BHI (2 * TILE_A_B)
#define OFF_BLO (2 * TILE_A_B + TILE_B_B)
#define STAGE_B (2 * TILE_A_B + 2 * TILE_B_B)  // 24576
#define GSMEM_TOTAL (3 * STAGE_B)              // 73728

template<int NP>
__global__ __launch_bounds__(256, 3) void gemm_hmma(
    const __half* __restrict__ Ahi, const __half* __restrict__ Alo,
    const __half* __restrict__ BhiT, const __half* __restrict__ BloT,
    float* __restrict__ C)
{
    extern __shared__ __align__(128) char smem[];
    const uint32_t sb = smem_u32(smem);
    const int t   = threadIdx.x;
    const int l   = t & 31;
    const int wid = t >> 5;
    const int wm  = wid >> 1;            // 0..3 -> m offset wm*32
    const int wn  = wid & 1;             // 0..1 -> n offset wn*32
    const int m0  = blockIdx.y * 128;
    const int n0  = blockIdx.x * 64;

    // A ldsm4 lane components
    const int arow = (l & 7) + ((l >> 3) & 1) * 8;
    const int ak8  = (l >> 4);
    // B paired ldsm4 lane components (2 n-tiles per instruction)
    const int bprow = (l >> 4) * 8 + (l & 7);
    const int bpk8  = (l >> 3) & 1;

    float acc[2][4][4];
#pragma unroll
    for (int i = 0; i < 2; ++i)
#pragma unroll
        for (int j = 0; j < 4; ++j)
#pragma unroll
            for (int u = 0; u < 4; ++u) acc[i][j][u] = 0.f;

    // chunk map: 1536 data chunks/stage: [0,512) Ahi, [512,1024) Alo,
    // [1024,1280) Bhi, [1280,1536) Blo. i=2,3 cover Alo exactly -> skipped NP2.
    auto load_tiles = [&](int kt, int s) {
        const uint32_t st = sb + s * STAGE_B;
#pragma unroll
        for (int i = 0; i < 6; ++i) {
            if (NP == 2 && (i == 2 || i == 3)) continue;
            int c = t + 256 * i;
            const __half* src;
            uint32_t toff;
            int rbase, local;
            if (c < 512)        { src = Ahi;  toff = OFF_AHI; rbase = m0; local = c; }
            else if (c < 1024)  { src = Alo;  toff = OFF_ALO; rbase = m0; local = c - 512; }
            else if (c < 1280)  { src = BhiT; toff = OFF_BHI; rbase = n0; local = c - 1024; }
            else                { src = BloT; toff = OFF_BLO; rbase = n0; local = c - 1280; }
            int row = local >> 2, ch = local & 3;
            cp16(st + toff + sw64(row, ch),
                 src + (size_t)(rbase + row) * Dc + kt * GKT + ch * 8);
        }
    };

    const int NT = Dc / GKT;             // 64
    load_tiles(0, 0); CP_COMMIT();
    load_tiles(1, 1); CP_COMMIT();

    for (int kt = 0; kt < NT; ++kt) {
        CP_WAIT(1);
        __syncthreads();

        const uint32_t st = sb + (kt % 3) * STAGE_B;

#pragma unroll
        for (int ks = 0; ks < 2; ++ks) {
            uint32_t ah[2][4], al[2][4], bh[2][4], bl[2][4];
#pragma unroll
            for (int mt = 0; mt < 2; ++mt) {
                int ar = wm * 32 + mt * 16 + arow;
                int ac = 2 * ks + ak8;
                ldsm4(ah[mt], st + OFF_AHI + sw64(ar, ac));
                if (NP == 3)
                    ldsm4(al[mt], st + OFF_ALO + sw64(ar, ac));
            }
#pragma unroll
            for (int p = 0; p < 2; ++p) {
                int br = wn * 32 + p * 16 + bprow;
                int bc = 2 * ks + bpk8;
                ldsm4(bh[p], st + OFF_BHI + sw64(br, bc));
                ldsm4(bl[p], st + OFF_BLO + sw64(br, bc));
            }
#pragma unroll
            for (int mt = 0; mt < 2; ++mt)
#pragma unroll
                for (int nt = 0; nt < 4; ++nt)
                    mma16816(acc[mt][nt], ah[mt], &bh[nt >> 1][(nt & 1) * 2]);
#pragma unroll
            for (int mt = 0; mt < 2; ++mt)
#pragma unroll
                for (int nt = 0; nt < 4; ++nt)
                    mma16816(acc[mt][nt], ah[mt], &bl[nt >> 1][(nt & 1) * 2]);
            if (NP == 3) {
#pragma unroll
                for (int mt = 0; mt < 2; ++mt)
#pragma unroll
                    for (int nt = 0; nt < 4; ++nt)
                        mma16816(acc[mt][nt], al[mt], &bh[nt >> 1][(nt & 1) * 2]);
            }
        }

        if (kt + 2 < NT) load_tiles(kt + 2, (kt + 2) % 3);
        CP_COMMIT();                      // empty group at tail keeps ordering
    }

    const int erow = m0 + wm * 32 + (l >> 2);
    const int ecol = n0 + wn * 32 + (l & 3) * 2;
#pragma unroll
    for (int mt = 0; mt < 2; ++mt)
#pragma unroll
        for (int nt = 0; nt < 4; ++nt) {
            *(float2*)&C[(size_t)(erow + mt * 16) * Dc + ecol + nt * 8] =
                make_float2(acc[mt][nt][0], acc[mt][nt][1]);
            *(float2*)&C[(size_t)(erow + mt * 16 + 8) * Dc + ecol + nt * 8] =
                make_float2(acc[mt][nt][2], acc[mt][nt][3]);
        }
}

// ---------------------------------------------------------------------------
// Rotary + fp16 hi/lo split: fp32 [b][s][h*128+d] -> fp16 [b][h][s][128]
// ---------------------------------------------------------------------------
__global__ void rotary_split(const float* __restrict__ q, const float* __restrict__ k,
                             __half* __restrict__ qhi, __half* __restrict__ qlo,
                             __half* __restrict__ khi, __half* __restrict__ klo)
{
    int idx = blockIdx.x * blockDim.x + threadIdx.x;
    if (idx >= Bc * Sc * Hc * 64) return;
    int j = idx & 63;
    int h = (idx >> 6) & (Hc - 1);
    int s = (idx >> 10) & (Sc - 1);
    int b = idx >> 21;

    float inv_freq = 1.0f / powf(10000.0f, (float)j * (1.0f / 64.0f));
    float sn, cs;
    sincosf((float)s * inv_freq, &sn, &cs);

    size_t ib = ((size_t)(b * Sc + s)) * Dc + h * HDc + j;
    size_t ob = ((size_t)((b * Hc + h) * Sc + s)) * HDc + j;

    float q1 = q[ib], q2 = q[ib + 64];
    float qa = q1 * cs - q2 * sn;
    float qb = q2 * cs + q1 * sn;
    float k1 = k[ib], k2 = k[ib + 64];
    float ka = k1 * cs - k2 * sn;
    float kb = k2 * cs + k1 * sn;

    __half hqa = __float2half(qa), hqb = __float2half(qb);
    __half hka = __float2half(ka), hkb = __float2half(kb);
    qhi[ob] = hqa;      qhi[ob + 64] = hqb;
    qlo[ob] = __float2half(qa - __half2float(hqa));
    qlo[ob + 64] = __float2half(qb - __half2float(hqb));
    khi[ob] = hka;      khi[ob + 64] = hkb;
    klo[ob] = __float2half(ka - __half2float(hka));
    klo[ob + 64] = __float2half(kb - __half2float(hkb));
}

// ---------------------------------------------------------------------------
// V split: fp32 [b][s][h*128+d] -> fp16 hi/lo [b][h][s][128]
// ---------------------------------------------------------------------------
__global__ void v_split(const float* __restrict__ v,
                        __half* __restrict__ vhi, __half* __restrict__ vlo)
{
    int idx = blockIdx.x * blockDim.x + threadIdx.x;
    if (idx >= TOTE / 2) return;
    int d2 = idx & 63;
    int h = (idx >> 6) & (Hc - 1);
    int s = (idx >> 10) & (Sc - 1);
    int b = idx >> 21;
    const float2 vv = *(const float2*)&v[((size_t)(b * Sc + s)) * Dc + h * HDc + d2 * 2];
    uint32_t hp, lp;
    splitpack(vv.x, vv.y, hp, lp);
    size_t ob = ((size_t)((b * Hc + h) * Sc + s)) * HDc + d2 * 2;
    *(uint32_t*)&vhi[ob] = hp;
    *(uint32_t*)&vlo[ob] = lp;
}

// ---------------------------------------------------------------------------
// Flash attention on HMMA: QK 3-product, PV 2-product (P single fp16),
// causal + tanh cap + Lingvo softmax (phantom 0-logit: m=0, l=1).
// CTA: 128 q rows x KV tiles of 64; 8 warps.
// Q fragments held in REGISTERS (loaded once); Q smem region reused as the
// third KV stage -> 3-stage cp.async, ONE barrier per iteration.
// ---------------------------------------------------------------------------
#define FST_B 65536                       // per-stage: Kh,Kl,Vh,Vl x 16KB
#define FSM_TOT (3 * FST_B)               // 196608 = 192KB

__global__ __launch_bounds__(256) void flash_mma(
    const __half* __restrict__ qhi, const __half* __restrict__ qlo,
    const __half* __restrict__ khi, const __half* __restrict__ klo,
    const __half* __restrict__ vhi, const __half* __restrict__ vlo,
    __half* __restrict__ Ohi)
{
    extern __shared__ __align__(128) char smem[];
    const uint32_t sb = smem_u32(smem);
    const int t = threadIdx.x, l = t & 31, w = t >> 5;
    const int qi = (Sc / 128 - 1) - blockIdx.x;        // heavy CTAs first
    const int h = blockIdx.y, b = blockIdx.z;
    const size_t hb = (size_t)(b * Hc + h) * Sc * HDc;

    // ---- stage 1: load Q into smem (temporarily), extract frags to regs ----
    const int aRow = 16 * w + (l & 15);
    const int aK8  = l >> 4;

#pragma unroll
    for (int i = 0; i < 8; ++i) {
        int c = t + 256 * i;                 // 0..2047 chunks of 16B
        int row = c >> 4, c16 = c & 15;
        uint32_t dst = (uint32_t)(row * 256 + ((c16 ^ (row & 7)) * 16));
        size_t src = hb + (size_t)(qi * 128 + row) * HDc + c16 * 8;
        cp16(sb + dst, qhi + src);
        cp16(sb + 32768 + dst, qlo + src);
    }
    CP_COMMIT();
    CP_WAIT(0);
    __syncthreads();

    uint32_t qfh[8][4], qfl[8][4];
#pragma unroll
    for (int k = 0; k < 8; ++k) {
        int ac16 = 2 * k + aK8;
        uint32_t aoff = (uint32_t)(aRow * 256 + ((ac16 ^ (aRow & 7)) * 16));
        ldsm4(qfh[k], sb + aoff);
        ldsm4(qfl[k], sb + 32768 + aoff);
    }
    __syncthreads();                        // all warps done reading Q region

    // ---- KV pipeline (3 stages, dist-2 prefetch) ----
    auto load_kv = [&](int j, int st) {
        uint32_t stb = sb + st * FST_B;
#pragma unroll
        for (int i = 0; i < 4; ++i) {
            int c = t + 256 * i;
            int row = c >> 4, c16 = c & 15;
            uint32_t dst = (uint32_t)(row * 256 + ((c16 ^ (row & 7)) * 16));
            size_t src = hb + (size_t)(j * 64 + row) * HDc + c16 * 8;
            cp16(stb + dst,         khi + src);
            cp16(stb + 16384 + dst, klo + src);
            cp16(stb + 32768 + dst, vhi + src);
            cp16(stb + 49152 + dst, vlo + src);
        }
    };

    const int nt = 2 * qi + 2;
    load_kv(0, 0); CP_COMMIT();
    if (nt > 1) load_kv(1, 1);
    CP_COMMIT();

    float accO[16][4];
#pragma unroll
    for (int n = 0; n < 16; ++n)
#pragma unroll
        for (int e = 0; e < 4; ++e) accO[n][e] = 0.f;
    float m0 = 0.f, m1 = 0.f, l0 = 1.f, l1 = 1.f;

    const int kRowL = (l >> 4) * 8 + (l & 7);
    const int kK8   = (l >> 3) & 1;
    const int vRow0 = (l & 7) + 8 * ((l >> 3) & 1);
    const int vC    = l >> 4;

    for (int j = 0; j < nt; ++j) {
        CP_WAIT(1);
        __syncthreads();

        const uint32_t stb = sb + (j % 3) * FST_B;
        const uint32_t sKh = stb, sKl = stb + 16384;
        const uint32_t sVh = stb + 32768, sVl = stb + 49152;

        // ---- S = Q K^T (3-product), Q from registers ----
        float accS[8][4];
#pragma unroll
        for (int n = 0; n < 8; ++n)
#pragma unroll
            for (int e = 0; e < 4; ++e) accS[n][e] = 0.f;

#pragma unroll
        for (int k = 0; k < 8; ++k) {
#pragma unroll
            for (int p = 0; p < 4; ++p) {
                int krow = 16 * p + kRowL;
                int kc16 = 2 * k + kK8;
                uint32_t boff = (uint32_t)(krow * 256 + ((kc16 ^ (krow & 7)) * 16));
                uint32_t bh4[4], bl4[4];
                ldsm4(bh4, sKh + boff);
                ldsm4(bl4, sKl + boff);
                mma16816(accS[2 * p],     qfh[k], &bh4[0]);
                mma16816(accS[2 * p + 1], qfh[k], &bh4[2]);
                mma16816(accS[2 * p],     qfh[k], &bl4[0]);
                mma16816(accS[2 * p + 1], qfh[k], &bl4[2]);
                mma16816(accS[2 * p],     qfl[k], &bh4[0]);
                mma16816(accS[2 * p + 1], qfl[k], &bh4[2]);
            }
        }

        // ---- tanh cap + causal mask (fast math) ----
#pragma unroll
        for (int n = 0; n < 8; ++n)
#pragma unroll
            for (int e = 0; e < 4; ++e)
                accS[n][e] = cap50(accS[n][e]);

        if (j >= 2 * qi) {
            int r0 = 16 * w + (l >> 2);
            int cb = j * 64 - qi * 128 + 2 * (l & 3);
#pragma unroll
            for (int n = 0; n < 8; ++n) {
                int c = cb + 8 * n;
                if (c     > r0)     accS[n][0] = -50.f;
                if (c + 1 > r0)     accS[n][1] = -50.f;
                if (c     > r0 + 8) accS[n][2] = -50.f;
                if (c + 1 > r0 + 8) accS[n][3] = -50.f;
            }
        }

        // ---- online softmax ----
        float mx0 = -1e30f, mx1 = -1e30f;
#pragma unroll
        for (int n = 0; n < 8; ++n) {
            mx0 = fmaxf(mx0, fmaxf(accS[n][0], accS[n][1]));
            mx1 = fmaxf(mx1, fmaxf(accS[n][2], accS[n][3]));
        }
        mx0 = fmaxf(mx0, __shfl_xor_sync(0xffffffffu, mx0, 1));
        mx0 = fmaxf(mx0, __shfl_xor_sync(0xffffffffu, mx0, 2));
        mx1 = fmaxf(mx1, __shfl_xor_sync(0xffffffffu, mx1, 1));
        mx1 = fmaxf(mx1, __shfl_xor_sync(0xffffffffu, mx1, 2));
        float mn0 = fmaxf(m0, mx0), mn1 = fmaxf(m1, mx1);
        float sc0 = __expf(m0 - mn0), sc1 = __expf(m1 - mn1);
        float rs0 = 0.f, rs1 = 0.f;
#pragma unroll
        for (int n = 0; n < 8; ++n) {
            accS[n][0] = __expf(accS[n][0] - mn0); rs0 += accS[n][0];
            accS[n][1] = __expf(accS[n][1] - mn0); rs0 += accS[n][1];
            accS[n][2] = __expf(accS[n][2] - mn1); rs1 += accS[n][2];
            accS[n][3] = __expf(accS[n][3] - mn1); rs1 += accS[n][3];
        }
        rs0 += __shfl_xor_sync(0xffffffffu, rs0, 1);
        rs0 += __shfl_xor_sync(0xffffffffu, rs0, 2);
        rs1 += __shfl_xor_sync(0xffffffffu, rs1, 1);
        rs1 += __shfl_xor_sync(0xffffffffu, rs1, 2);
        l0 = l0 * sc0 + rs0;  m0 = mn0;
        l1 = l1 * sc1 + rs1;  m1 = mn1;
#pragma unroll
        for (int n = 0; n < 16; ++n) {
            accO[n][0] *= sc0; accO[n][1] *= sc0;
            accO[n][2] *= sc1; accO[n][3] *= sc1;
        }

        // ---- O += P V (2-product: P fp16 single, V 2-split, paired ldsm4t) ----
#pragma unroll
        for (int kk = 0; kk < 4; ++kk) {
            uint32_t pa[4];
            pa[0] = pack2h(accS[2 * kk][0],     accS[2 * kk][1]);
            pa[1] = pack2h(accS[2 * kk][2],     accS[2 * kk][3]);
            pa[2] = pack2h(accS[2 * kk + 1][0], accS[2 * kk + 1][1]);
            pa[3] = pack2h(accS[2 * kk + 1][2], accS[2 * kk + 1][3]);
            int vrow = 16 * kk + vRow0;
#pragma unroll
            for (int np = 0; np < 8; ++np) {
                int vc16 = (2 * np + vC) ^ (vrow & 7);
                uint32_t voff = (uint32_t)(vrow * 256 + vc16 * 16);
                uint32_t vh4[4], vl4[4];
                ldsm4t(vh4, sVh + voff);
                ldsm4t(vl4, sVl + voff);
                mma16816(accO[2 * np],     pa, &vh4[0]);
                mma16816(accO[2 * np + 1], pa, &vh4[2]);
                mma16816(accO[2 * np],     pa, &vl4[0]);
                mma16816(accO[2 * np + 1], pa, &vl4[2]);
            }
        }

        if (j + 2 < nt) load_kv(j + 2, (j + 2) % 3);
        CP_COMMIT();                      // empty group at tail keeps ordering
    }

    // ---- write O as fp16 (hi only) in [b][s][h*128+d] layout ----
    float i0 = 1.f / l0, i1 = 1.f / l1;
    int row0 = qi * 128 + 16 * w + (l >> 2);
    size_t ob0 = ((size_t)b * Sc + row0) * Dc + h * HDc;
    size_t ob1 = ob0 + 8 * (size_t)Dc;
#pragma unroll
    for (int n = 0; n < 16; ++n) {
        int d = 8 * n + 2 * (l & 3);
        *(uint32_t*)&Ohi[ob0 + d] = pack2h(accO[n][0] * i0, accO[n][1] * i0);
        *(uint32_t*)&Ohi[ob1 + d] = pack2h(accO[n][2] * i1, accO[n][3] * i1);
    }
}

// ---------------------------------------------------------------------------
extern "C" void kernel_launch(void* const* d_in, const int* in_sizes, int n_in,
                              void* d_out, int out_size)
{
    const float* hidden = (const float*)d_in[0];
    const float* wq = (const float*)d_in[1];
    const float* wk = (const float*)d_in[2];
    const float* wv = (const float*)d_in[3];
    const float* wo = (const float*)d_in[4];
    float* out = (float*)d_out;

    float *q, *k, *v;
    __half *xhi, *xlo, *whiT, *wloT;
    __half *qhi, *qlo, *khi, *klo, *vhi, *vlo;
    cudaGetSymbolAddress((void**)&q, g_q);
    cudaGetSymbolAddress((void**)&k, g_k);
    cudaGetSymbolAddress((void**)&v, g_v);
    cudaGetSymbolAddress((void**)&xhi, g_xhi);
    cudaGetSymbolAddress((void**)&xlo, g_xlo);
    cudaGetSymbolAddress((void**)&whiT, g_whiT);
    cudaGetSymbolAddress((void**)&wloT, g_wloT);
    cudaGetSymbolAddress((void**)&qhi, g_qhi);
    cudaGetSymbolAddress((void**)&qlo, g_qlo);
    cudaGetSymbolAddress((void**)&khi, g_khi);
    cudaGetSymbolAddress((void**)&klo, g_klo);
    cudaGetSymbolAddress((void**)&vhi, g_vhi);
    cudaGetSymbolAddress((void**)&vlo, g_vlo);

    cudaFuncSetAttribute(gemm_hmma<3>, cudaFuncAttributeMaxDynamicSharedMemorySize, GSMEM_TOTAL);
    cudaFuncSetAttribute(gemm_hmma<2>, cudaFuncAttributeMaxDynamicSharedMemorySize, GSMEM_TOTAL);
    cudaFuncSetAttribute(flash_mma, cudaFuncAttributeMaxDynamicSharedMemorySize, FSM_TOT);

    // 1. splits
    conv_split<<<(TOTE / 4 + 255) / 256, 256>>>(hidden, xhi, xlo, TOTE / 4);
    conv_w_all<<<dim3(Dc / 32, Dc / 32, 4), dim3(32, 8)>>>(wq, wk, wv, wo, whiT, wloT);

    // 2. QKV projections (Q,K 3-product; V 2-product)
    dim3 ggrid(Dc / 64, MTOT / 128);     // (32, 32)
    gemm_hmma<3><<<ggrid, 256, GSMEM_TOTAL>>>(xhi, xlo, whiT + 0 * DD, wloT + 0 * DD, q);
    gemm_hmma<3><<<ggrid, 256, GSMEM_TOTAL>>>(xhi, xlo, whiT + 1 * DD, wloT + 1 * DD, k);
    gemm_hmma<2><<<ggrid, 256, GSMEM_TOTAL>>>(xhi, xlo, whiT + 2 * DD, wloT + 2 * DD, v);

    // 3. rotary + splits for attention
    rotary_split<<<(Bc * Sc * Hc * 64) / 256, 256>>>(q, k, qhi, qlo, khi, klo);
    v_split<<<(TOTE / 2) / 256, 256>>>(v, vhi, vlo);

    // 4. attention — writes xhi (fp16 O) for the output projection
    flash_mma<<<dim3(Sc / 128, Hc, Bc), 256, FSM_TOT>>>(qhi, qlo, khi, klo, vhi, vlo, xhi);

    // 5. output projection (2-product)
    gemm_hmma<2><<<ggrid, 256, GSMEM_TOTAL>>>(xhi, xlo, whiT + 3 * DD, wloT + 3 * DD, out);
}